// round 1
// baseline (speedup 1.0000x reference)
#include <cuda_runtime.h>
#include <cstddef>

// ============================================================================
// Problem constants
// ============================================================================
#define NB   8          // batch
#define NE   2          // per-voxel entries (two diameters)
#define NG   (NB*NE)    // 16 groups
#define NXC  32
#define NYC  32
#define NZC  8
#define NC   (NXC*NYC*NZC)   // 8192 cells
#define GMAX NC

static __device__ __constant__ float c_LATX = 25.0f/32.0f;
static __device__ __constant__ float c_LATY = 25.0f/32.0f;
static __device__ __constant__ float c_LATZ = 3.0f/8.0f;

// ============================================================================
// Device scratch (allocations are forbidden -> __device__ globals)
// ============================================================================
__device__ float g_pred [NG][GMAX][4];   // masked preds, cell order
__device__ float g_ppos [NG][GMAX][3];
__device__ float g_bbp  [NG][GMAX];      // |ppos|^2 (reduce-order)
__device__ float g_tgt  [NG][GMAX][4];   // masked targets, cell order
__device__ float g_tpos [NG][GMAX][3];
__device__ float g_bbt  [NG][GMAX];
__device__ int   g_Np[NG], g_Nt[NG];

__device__ float g_spred[NG][GMAX][4];   // sorted ascending by prob
__device__ float g_spos [NG][GMAX][3];
__device__ float g_bbs  [NG][GMAX];
__device__ int   g_restrain[NG][GMAX];
__device__ int   g_sel  [NG][GMAX];

__device__ float g_npred[NG][GMAX][4];   // NMS survivors
__device__ float g_npos [NG][GMAX][3];
__device__ float g_bbn  [NG][GMAX];
__device__ int   g_Ns[NG];

__device__ int g_thas [NG][GMAX], g_targ [NG][GMAX];   // full match per target
__device__ int g_thasn[NG][GMAX], g_targn[NG][GMAX];   // nms match per target
__device__ int g_ti[NG][GMAX], g_pi[NG][GMAX];
__device__ int g_tin[NG][GMAX], g_pin[NG][GMAX];
__device__ int g_L[NG], g_Ln[NG];

__device__ long long g_off[NG][10];
__device__ float g_thr2[NE];   // d2 threshold equivalent to sqrt(max(d2,0)) < diam

// ============================================================================
// Exact-rounding helpers (mirror the reference's fp32 evaluation order)
//   ab: fma chain k=0,1,2 (GEMM-style accumulation)
//   aa/bb: non-fused mul + left-to-right add (elementwise-square + reduce)
//   d2 = (aa+bb) - 2*ab   (2*ab exact scale)
// ============================================================================
__device__ __forceinline__ float dot3(float ax,float ay,float az,
                                      float bx,float by,float bz){
    return __fmaf_rn(az,bz,__fmaf_rn(ay,by,__fmul_rn(ax,bx)));
}
__device__ __forceinline__ float nrm3(float x,float y,float z){
    return __fadd_rn(__fadd_rn(__fmul_rn(x,x),__fmul_rn(y,y)),__fmul_rn(z,z));
}
__device__ __forceinline__ float d2of(float aa,float bb,float ab){
    return __fsub_rn(__fadd_rn(aa,bb), __fadd_rn(ab,ab));
}

// ============================================================================
// Kernel 0: bit-search the d2 threshold so that  (d2 < thr2) <=> (sqrtf(max(d2,0)) < diam)
// ============================================================================
__global__ void k_init(){
    int e = threadIdx.x;
    if (e < NE){
        float diam = (e==0) ? (float)(0.74*1.4) : (float)(0.528*1.4);
        float d2 = diam*diam;
        unsigned lo = __float_as_uint(d2*0.5f);
        unsigned hi = __float_as_uint(d2*2.0f);
        // invariant: sqrtf(lo) < diam, sqrtf(hi) >= diam (positive floats order as uints)
        while (lo + 1u < hi){
            unsigned mid = lo + ((hi - lo) >> 1);
            if (sqrtf(__uint_as_float(mid)) >= diam) hi = mid; else lo = mid;
        }
        g_thr2[e] = __uint_as_float(hi);
    }
}

// ============================================================================
// Kernel 1: stable mask compaction per group (one block of 1024, 8 cells/thread)
// ============================================================================
__global__ void __launch_bounds__(1024) k_compact(const float* __restrict__ P,
                                                  const float* __restrict__ T){
    int g = blockIdx.x, b = g >> 1, e = g & 1, t = threadIdx.x;
    __shared__ int shp[1024], sht[1024];

    unsigned mpm = 0, mtm = 0;
    int cp = 0, ct = 0;
    #pragma unroll
    for (int r = 0; r < 8; r++){
        int c = t*8 + r;
        size_t base = (((size_t)(b*NC + c))*2 + (size_t)e)*4;
        if (P[base+3] > 0.5f){ mpm |= 1u << r; cp++; }
        if (T[base+3] > 0.5f){ mtm |= 1u << r; ct++; }
    }
    shp[t] = cp; sht[t] = ct; __syncthreads();
    for (int o = 1; o < 1024; o <<= 1){
        int a = 0, b2 = 0;
        if (t >= o){ a = shp[t-o]; b2 = sht[t-o]; }
        __syncthreads();
        shp[t] += a; sht[t] += b2;
        __syncthreads();
    }
    int op = shp[t] - cp, ot = sht[t] - ct;
    if (t == 1023){ g_Np[g] = shp[1023]; g_Nt[g] = sht[1023]; }

    #pragma unroll
    for (int r = 0; r < 8; r++){
        int c = t*8 + r;
        int ci = c >> 8, cj = (c >> 3) & 31, ck = c & 7;
        size_t base = (((size_t)(b*NC + c))*2 + (size_t)e)*4;
        if ((mpm >> r) & 1u){
            float v0 = P[base], v1 = P[base+1], v2 = P[base+2], v3 = P[base+3];
            g_pred[g][op][0]=v0; g_pred[g][op][1]=v1; g_pred[g][op][2]=v2; g_pred[g][op][3]=v3;
            float px = __fmul_rn(__fadd_rn(v0,(float)ci), c_LATX);
            float py = __fmul_rn(__fadd_rn(v1,(float)cj), c_LATY);
            float pz = __fmul_rn(__fadd_rn(v2,(float)ck), c_LATZ);
            g_ppos[g][op][0]=px; g_ppos[g][op][1]=py; g_ppos[g][op][2]=pz;
            g_bbp[g][op] = nrm3(px,py,pz);
            op++;
        }
        if ((mtm >> r) & 1u){
            float v0 = T[base], v1 = T[base+1], v2 = T[base+2], v3 = T[base+3];
            g_tgt[g][ot][0]=v0; g_tgt[g][ot][1]=v1; g_tgt[g][ot][2]=v2; g_tgt[g][ot][3]=v3;
            float px = __fmul_rn(__fadd_rn(v0,(float)ci), c_LATX);
            float py = __fmul_rn(__fadd_rn(v1,(float)cj), c_LATY);
            float pz = __fmul_rn(__fadd_rn(v2,(float)ck), c_LATZ);
            g_tpos[g][ot][0]=px; g_tpos[g][ot][1]=py; g_tpos[g][ot][2]=pz;
            g_bbt[g][ot] = nrm3(px,py,pz);
            ot++;
        }
    }
}

// ============================================================================
// Kernel 2: stable ascending rank-sort by probability (O(n^2), shared broadcast)
//   grid: NG*8 blocks of 1024 (8192 slots/group)
// ============================================================================
__global__ void __launch_bounds__(1024) k_sort(){
    int g = blockIdx.x >> 3;
    int Np = g_Np[g];
    __shared__ float sh[GMAX];   // 32 KB
    for (int i = threadIdx.x; i < Np; i += 1024) sh[i] = g_pred[g][i][3];
    __syncthreads();
    int i = (blockIdx.x & 7)*1024 + threadIdx.x;
    if (i >= Np) return;
    float v = sh[i];
    int r = 0;
    for (int j = 0; j < Np; j++){
        float u = sh[j];
        r += (u < v) || (u == v && j < i);
    }
    #pragma unroll
    for (int c = 0; c < 4; c++) g_spred[g][r][c] = g_pred[g][i][c];
    float x = g_ppos[g][i][0], y = g_ppos[g][i][1], z = g_ppos[g][i][2];
    g_spos[g][r][0]=x; g_spos[g][r][1]=y; g_spos[g][r][2]=z;
    g_bbs[g][r] = nrm3(x,y,z);
}

// ============================================================================
// Kernel 3: restrain[j] = #{i<j : dist(sp_i, sp_j) < diam}
// ============================================================================
__global__ void __launch_bounds__(1024) k_restrain(){
    int g = blockIdx.x >> 3, e = g & 1;
    int Np = g_Np[g];
    int j = (blockIdx.x & 7)*1024 + threadIdx.x;
    if (j >= Np) return;
    float thr = g_thr2[e];
    float jx = g_spos[g][j][0], jy = g_spos[g][j][1], jz = g_spos[g][j][2];
    float aj = g_bbs[g][j];
    int cnt = 0;
    for (int i = 0; i < j; i++){
        float ab = dot3(g_spos[g][i][0], g_spos[g][i][1], g_spos[g][i][2], jx, jy, jz);
        float d2 = d2of(aj, g_bbs[g][i], ab);
        cnt += (d2 < thr);
    }
    g_restrain[g][j] = cnt;
}

// ============================================================================
// Kernel 4: correct[j] and sel[j] = (restrain[j] == correct[j])
// ============================================================================
__global__ void __launch_bounds__(1024) k_correct(){
    int g = blockIdx.x >> 3, e = g & 1;
    int Np = g_Np[g];
    int j = (blockIdx.x & 7)*1024 + threadIdx.x;
    if (j >= Np) return;
    float thr = g_thr2[e];
    float jx = g_spos[g][j][0], jy = g_spos[g][j][1], jz = g_spos[g][j][2];
    float aj = g_bbs[g][j];
    int cnt = 0;
    for (int i = 0; i < j; i++){
        float ab = dot3(g_spos[g][i][0], g_spos[g][i][1], g_spos[g][i][2], jx, jy, jz);
        float d2 = d2of(aj, g_bbs[g][i], ab);
        cnt += (d2 < thr) && (g_restrain[g][i] != 0);
    }
    g_sel[g][j] = (g_restrain[g][j] == cnt) ? 1 : 0;
}

// ============================================================================
// Kernel 5: compact NMS survivors (stable, one block/group)
// ============================================================================
__global__ void __launch_bounds__(1024) k_nmsc(){
    int g = blockIdx.x, t = threadIdx.x;
    int Np = g_Np[g];
    __shared__ int sh[1024];
    int cnt = 0;
    #pragma unroll
    for (int r = 0; r < 8; r++){
        int i = t*8 + r;
        if (i < Np && g_sel[g][i]) cnt++;
    }
    sh[t] = cnt; __syncthreads();
    for (int o = 1; o < 1024; o <<= 1){
        int a = 0;
        if (t >= o) a = sh[t-o];
        __syncthreads();
        sh[t] += a;
        __syncthreads();
    }
    int off = sh[t] - cnt;
    if (t == 1023) g_Ns[g] = sh[1023];
    #pragma unroll
    for (int r = 0; r < 8; r++){
        int i = t*8 + r;
        if (i < Np && g_sel[g][i]){
            #pragma unroll
            for (int c = 0; c < 4; c++) g_npred[g][off][c] = g_spred[g][i][c];
            #pragma unroll
            for (int c = 0; c < 3; c++) g_npos[g][off][c] = g_spos[g][i][c];
            g_bbn[g][off] = g_bbs[g][i];
            off++;
        }
    }
}

// ============================================================================
// Kernel 6/7: per-target match (any d<diam; first-occurrence argmin of sqrt row).
// Lazy sqrt: only evaluated on strict new d2 minima -> provably identical to
// argmin over rn(sqrt(max(d2,0))) with first-occurrence ties.
// ============================================================================
__global__ void __launch_bounds__(1024) k_match(int use_nms){
    int g = blockIdx.x >> 3, e = g & 1;
    int Nt = g_Nt[g];
    int Np = use_nms ? g_Ns[g] : g_Np[g];
    int t = (blockIdx.x & 7)*1024 + threadIdx.x;
    if (t >= Nt) return;
    const float (*pp)[3] = use_nms ? g_npos[g] : g_ppos[g];
    const float* bb      = use_nms ? g_bbn[g]  : g_bbp[g];
    float thr = g_thr2[e];
    float tx = g_tpos[g][t][0], ty = g_tpos[g][t][1], tz = g_tpos[g][t][2];
    float at = g_bbt[g][t];
    int has = 0, arg = 0;
    float d2min = 3.4028235e38f, smin = 3.4028235e38f;
    for (int p = 0; p < Np; p++){
        float ab = dot3(pp[p][0], pp[p][1], pp[p][2], tx, ty, tz);
        float d2 = d2of(at, bb[p], ab);
        has |= (d2 < thr);
        if (d2 < d2min){
            float s = sqrtf(fmaxf(d2, 0.0f));
            if (s < smin){ smin = s; arg = p; }
            d2min = d2;
        }
    }
    if (use_nms){ g_thasn[g][t] = has; g_targn[g][t] = arg; }
    else        { g_thas [g][t] = has; g_targ [g][t] = arg; }
}

// ============================================================================
// Kernel 8: compact (ti, pi) and (ti_n, pi_n)  (stable, one block/group)
// ============================================================================
__global__ void __launch_bounds__(1024) k_matchc(){
    int g = blockIdx.x, t = threadIdx.x;
    int Nt = g_Nt[g];
    __shared__ int s1[1024], s2[1024];
    int c1 = 0, c2 = 0;
    #pragma unroll
    for (int r = 0; r < 8; r++){
        int i = t*8 + r;
        if (i < Nt){ c1 += g_thas[g][i]; c2 += g_thasn[g][i]; }
    }
    s1[t] = c1; s2[t] = c2; __syncthreads();
    for (int o = 1; o < 1024; o <<= 1){
        int a = 0, b = 0;
        if (t >= o){ a = s1[t-o]; b = s2[t-o]; }
        __syncthreads();
        s1[t] += a; s2[t] += b;
        __syncthreads();
    }
    int o1 = s1[t] - c1, o2 = s2[t] - c2;
    if (t == 1023){ g_L[g] = s1[1023]; g_Ln[g] = s2[1023]; }
    #pragma unroll
    for (int r = 0; r < 8; r++){
        int i = t*8 + r;
        if (i < Nt){
            if (g_thas[g][i]) { g_ti [g][o1] = i; g_pi [g][o1] = g_targ [g][i]; o1++; }
            if (g_thasn[g][i]){ g_tin[g][o2] = i; g_pin[g][o2] = g_targn[g][i]; o2++; }
        }
    }
}

// ============================================================================
// Kernel 9: global output offsets (serial over 160 arrays — trivial)
// ============================================================================
__global__ void k_offsets(){
    if (threadIdx.x == 0 && blockIdx.x == 0){
        long long cur = 0;
        for (int g = 0; g < NG; g++){
            int Np = g_Np[g], Ns = g_Ns[g], Nt = g_Nt[g], L = g_L[g], Ln = g_Ln[g];
            long long sz[10] = { (long long)Np*4, (long long)Ns*4, (long long)Nt*4,
                                 L, L, Ln, Ln,
                                 (long long)Np*3, (long long)Ns*3, (long long)Nt*3 };
            for (int a = 0; a < 10; a++){ g_off[g][a] = cur; cur += sz[a]; }
        }
    }
}

// ============================================================================
// Kernel 10: writer — one block per (group, array)
// ============================================================================
__global__ void k_write(float* __restrict__ out){
    int g = blockIdx.x / 10, a = blockIdx.x % 10;
    int Np = g_Np[g], Ns = g_Ns[g], Nt = g_Nt[g], L = g_L[g], Ln = g_Ln[g];
    long long off = g_off[g][a];
    int n;
    switch (a){
        case 0: n = Np*4; break;
        case 1: n = Ns*4; break;
        case 2: n = Nt*4; break;
        case 3: case 4: n = L; break;
        case 5: case 6: n = Ln; break;
        case 7: n = Np*3; break;
        case 8: n = Ns*3; break;
        default: n = Nt*3; break;
    }
    for (int x = threadIdx.x; x < n; x += blockDim.x){
        float v;
        switch (a){
            case 0: v = g_pred [g][x>>2][x&3]; break;
            case 1: v = g_npred[g][x>>2][x&3]; break;
            case 2: v = g_tgt  [g][x>>2][x&3]; break;
            case 3: v = (float)g_ti [g][x]; break;
            case 4: v = (float)g_pi [g][x]; break;
            case 5: v = (float)g_tin[g][x]; break;
            case 6: v = (float)g_pin[g][x]; break;
            case 7: v = g_ppos[g][x/3][x%3]; break;
            case 8: v = g_npos[g][x/3][x%3]; break;
            default:v = g_tpos[g][x/3][x%3]; break;
        }
        out[off + x] = v;
    }
}

// ============================================================================
// Launch
// ============================================================================
extern "C" void kernel_launch(void* const* d_in, const int* in_sizes, int n_in,
                              void* d_out, int out_size){
    const float* P = (const float*)d_in[0];
    const float* T = (const float*)d_in[1];
    float* out = (float*)d_out;
    (void)in_sizes; (void)n_in; (void)out_size;

    k_init    <<<1, 32>>>();
    k_compact <<<NG, 1024>>>(P, T);
    k_sort    <<<NG*8, 1024>>>();
    k_restrain<<<NG*8, 1024>>>();
    k_correct <<<NG*8, 1024>>>();
    k_nmsc    <<<NG, 1024>>>();
    k_match   <<<NG*8, 1024>>>(0);
    k_match   <<<NG*8, 1024>>>(1);
    k_matchc  <<<NG, 1024>>>();
    k_offsets <<<1, 1>>>();
    k_write   <<<NG*10, 256>>>(out);
}

// round 4
// speedup vs baseline: 1.5779x; 1.5779x over previous
#include <cuda_runtime.h>
#include <cstddef>

// ============================================================================
// Problem constants
// ============================================================================
#define NB   8
#define NE   2
#define NG   16
#define NC   8192
#define GMAX 8192
#define FINF 3.4028235e38f

static __device__ __constant__ float c_LATX = 0.78125f;  // 25/32 exact
static __device__ __constant__ float c_LATY = 0.78125f;
static __device__ __constant__ float c_LATZ = 0.375f;    // 3/8 exact

// ============================================================================
// Device scratch (allocations forbidden -> __device__ globals)
// ============================================================================
__device__ float  g_pred [NG][GMAX][4];   // masked preds (cell order)
__device__ float4 g_ppos4[NG][GMAX];      // x,y,z,|p|^2
__device__ float  g_tgt  [NG][GMAX][4];
__device__ float4 g_tpos4[NG][GMAX];
__device__ int g_Np[NG], g_Nt[NG];
__device__ int g_ccp[NG][32], g_cct[NG][32];   // per-chunk mask counts
__device__ int g_cop[NG][32], g_cot[NG][32];   // per-chunk offsets

__device__ float  g_spred[NG][GMAX][4];   // sorted ascending by prob
__device__ float4 g_spos4[NG][GMAX];
__device__ int g_restrain[NG][GMAX];
__device__ int g_correct [NG][GMAX];

__device__ float  g_npred[NG][GMAX][4];   // NMS survivors
__device__ float4 g_npos4[NG][GMAX];
__device__ int g_Ns[NG];

// match partials per p-chunk (4 chunks of 2048), [0]=full, [1]=nms
__device__ float g_pd2[2][NG][GMAX][4];
__device__ float g_psm[2][NG][GMAX][4];
__device__ int   g_par[2][NG][GMAX][4];

__device__ int g_thas [NG][GMAX], g_targ [NG][GMAX];
__device__ int g_thasn[NG][GMAX], g_targn[NG][GMAX];
__device__ int g_ti[NG][GMAX], g_pi[NG][GMAX];
__device__ int g_tin[NG][GMAX], g_pin[NG][GMAX];
__device__ int g_L[NG], g_Ln[NG];

__device__ long long g_off[NG][10];
__device__ float g_thr2[NE];

// ============================================================================
// Rounding-exact helpers (validated: rel_err==0.0 in round 1)
// ============================================================================
__device__ __forceinline__ float nrm3(float x,float y,float z){
    return __fadd_rn(__fadd_rn(__fmul_rn(x,x),__fmul_rn(y,y)),__fmul_rn(z,z));
}

// ============================================================================
// k_init: bit-search d2 threshold s.t. (d2 < thr2) <=> (sqrtf(max(d2,0)) < diam)
// ============================================================================
__global__ void k_init(){
    int e = threadIdx.x;
    if (e < NE){
        float diam = (e==0) ? (float)(0.74*1.4) : (float)(0.528*1.4);
        float d2 = diam*diam;
        unsigned lo = __float_as_uint(d2*0.5f);
        unsigned hi = __float_as_uint(d2*2.0f);
        while (lo + 1u < hi){
            unsigned mid = lo + ((hi - lo) >> 1);
            if (sqrtf(__uint_as_float(mid)) >= diam) hi = mid; else lo = mid;
        }
        g_thr2[e] = __uint_as_float(hi);
    }
}

// ============================================================================
// k_zero: clear atomic accumulators (needed every graph replay)
// ============================================================================
__global__ void __launch_bounds__(512) k_zero(){
    int i = blockIdx.x*512 + threadIdx.x;
    if (i < NG*GMAX){
        ((int*)g_restrain)[i] = 0;
        ((int*)g_correct)[i]  = 0;
    }
}

// ============================================================================
// Compaction phase (parallel: count -> prefix -> scatter)
// ============================================================================
__global__ void __launch_bounds__(256) k_maskcnt(const float* __restrict__ P,
                                                 const float* __restrict__ T){
    int chunk = blockIdx.x, g = blockIdx.y, b = g >> 1, e = g & 1;
    int c = chunk*256 + threadIdx.x;
    size_t base = (((size_t)(b*NC + c))*2 + (size_t)e)*4;
    int mp = P[base+3] > 0.5f;
    int mt = T[base+3] > 0.5f;
    int cp = __syncthreads_count(mp);
    int ct = __syncthreads_count(mt);
    if (threadIdx.x == 0){ g_ccp[g][chunk] = cp; g_cct[g][chunk] = ct; }
}

__global__ void k_coffs(){
    int g = threadIdx.x;
    if (g < NG){
        int op = 0, ot = 0;
        for (int c = 0; c < 32; c++){
            g_cop[g][c] = op; op += g_ccp[g][c];
            g_cot[g][c] = ot; ot += g_cct[g][c];
        }
        g_Np[g] = op; g_Nt[g] = ot;
    }
}

__global__ void __launch_bounds__(256) k_scat(const float* __restrict__ P,
                                              const float* __restrict__ T){
    int chunk = blockIdx.x, g = blockIdx.y, b = g >> 1, e = g & 1;
    int tid = threadIdx.x;
    int c = chunk*256 + tid;
    size_t idx4 = ((size_t)(b*NC + c))*2 + (size_t)e;
    const float4* P4 = (const float4*)P;
    const float4* T4 = (const float4*)T;
    float4 pv = P4[idx4];
    float4 tv = T4[idx4];
    int mp = pv.w > 0.5f;
    int mt = tv.w > 0.5f;

    unsigned bp = __ballot_sync(0xffffffffu, mp);
    unsigned bt = __ballot_sync(0xffffffffu, mt);
    int lane = tid & 31, w = tid >> 5;
    __shared__ int wpo[8], wto[8];
    __shared__ int wpc[8], wtc[8];
    if (lane == 0){ wpc[w] = __popc(bp); wtc[w] = __popc(bt); }
    __syncthreads();
    if (tid == 0){
        int a = 0, b2 = 0;
        for (int k = 0; k < 8; k++){ wpo[k] = a; a += wpc[k]; wto[k] = b2; b2 += wtc[k]; }
    }
    __syncthreads();

    int ci = c >> 8, cj = (c >> 3) & 31, ck = c & 7;
    unsigned ltm = (1u << lane) - 1u;
    if (mp){
        int o = g_cop[g][chunk] + wpo[w] + __popc(bp & ltm);
        g_pred[g][o][0] = pv.x; g_pred[g][o][1] = pv.y;
        g_pred[g][o][2] = pv.z; g_pred[g][o][3] = pv.w;
        float px = __fmul_rn(__fadd_rn(pv.x,(float)ci), c_LATX);
        float py = __fmul_rn(__fadd_rn(pv.y,(float)cj), c_LATY);
        float pz = __fmul_rn(__fadd_rn(pv.z,(float)ck), c_LATZ);
        g_ppos4[g][o] = make_float4(px,py,pz, nrm3(px,py,pz));
    }
    if (mt){
        int o = g_cot[g][chunk] + wto[w] + __popc(bt & ltm);
        g_tgt[g][o][0] = tv.x; g_tgt[g][o][1] = tv.y;
        g_tgt[g][o][2] = tv.z; g_tgt[g][o][3] = tv.w;
        float px = __fmul_rn(__fadd_rn(tv.x,(float)ci), c_LATX);
        float py = __fmul_rn(__fadd_rn(tv.y,(float)cj), c_LATY);
        float pz = __fmul_rn(__fadd_rn(tv.z,(float)ck), c_LATZ);
        g_tpos4[g][o] = make_float4(px,py,pz, nrm3(px,py,pz));
    }
}

// ============================================================================
// k_sort: stable ascending rank-sort by prob.
// For j<i the condition (u<v)||(u==v&&j<i) collapses to (u<=v).
// ============================================================================
__global__ void __launch_bounds__(512) k_sort(){
    int ic = blockIdx.x, g = blockIdx.y;
    int Np = g_Np[g];
    __shared__ float sp[GMAX];
    for (int j = threadIdx.x; j < GMAX; j += 512)
        sp[j] = (j < Np) ? g_pred[g][j][3] : FINF;
    __syncthreads();
    int i = ic*512 + threadIdx.x;
    if (i >= Np) return;
    float v = sp[i];
    int r = 0;
    #pragma unroll 4
    for (int j = 0; j < i; j++)      r += (sp[j] <= v);
    #pragma unroll 4
    for (int j = i+1; j < Np; j++)   r += (sp[j] <  v);
    g_spred[g][r][0] = g_pred[g][i][0];
    g_spred[g][r][1] = g_pred[g][i][1];
    g_spred[g][r][2] = g_pred[g][i][2];
    g_spred[g][r][3] = g_pred[g][i][3];
    g_spos4[g][r] = g_ppos4[g][i];
}

// ============================================================================
// k_restrain: restrain[j] = #{i<j : d(i,j) < diam}   (tiled, 2 j/thread,
// i-slices across blocks, partial counts via integer atomicAdd)
// grid (jc=16, is=4, g=16), block 256
// ============================================================================
__global__ void __launch_bounds__(256) k_restrain(){
    int jc = blockIdx.x, is = blockIdx.y, g = blockIdx.z;
    int Np = g_Np[g];
    int jcbase = jc*512;
    if (jcbase >= Np) return;
    int jend = min(jcbase + 512, Np);
    int isbase = is*2048;
    if (isbase >= jend) return;

    __shared__ float4 tile[2048];
    int lim = min(2048, Np - isbase);
    for (int k = threadIdx.x; k < 2048; k += 256)
        tile[k] = (k < lim) ? g_spos4[g][isbase + k] : make_float4(0.f,0.f,0.f,FINF);
    __syncthreads();

    int tid = threadIdx.x;
    int j0 = jcbase + tid, j1 = jcbase + 256 + tid;
    bool v0 = j0 < Np, v1 = j1 < Np;
    float4 Q0 = v0 ? g_spos4[g][j0] : make_float4(0,0,0,0);
    float4 Q1 = v1 ? g_spos4[g][j1] : make_float4(0,0,0,0);
    float thr = g_thr2[g & 1];
    int c0 = 0, c1 = 0;

    if (isbase + 2048 <= jcbase){
        #pragma unroll 4
        for (int k = 0; k < 2048; k++){
            float4 f = tile[k];
            float ab0 = __fmaf_rn(f.z,Q0.z,__fmaf_rn(f.y,Q0.y,__fmul_rn(f.x,Q0.x)));
            float d20 = __fsub_rn(__fadd_rn(Q0.w,f.w), __fadd_rn(ab0,ab0));
            c0 += (d20 < thr);
            float ab1 = __fmaf_rn(f.z,Q1.z,__fmaf_rn(f.y,Q1.y,__fmul_rn(f.x,Q1.x)));
            float d21 = __fsub_rn(__fadd_rn(Q1.w,f.w), __fadd_rn(ab1,ab1));
            c1 += (d21 < thr);
        }
    } else {
        int b0 = v0 ? max(0, min(j0 - isbase, 2048)) : 0;
        int b1 = v1 ? max(0, min(j1 - isbase, 2048)) : 0;
        int e  = max(b0, b1);
        for (int k = 0; k < e; k++){
            float4 f = tile[k];
            float ab0 = __fmaf_rn(f.z,Q0.z,__fmaf_rn(f.y,Q0.y,__fmul_rn(f.x,Q0.x)));
            float d20 = __fsub_rn(__fadd_rn(Q0.w,f.w), __fadd_rn(ab0,ab0));
            if (k < b0 && d20 < thr) c0++;
            float ab1 = __fmaf_rn(f.z,Q1.z,__fmaf_rn(f.y,Q1.y,__fmul_rn(f.x,Q1.x)));
            float d21 = __fsub_rn(__fadd_rn(Q1.w,f.w), __fadd_rn(ab1,ab1));
            if (k < b1 && d21 < thr) c1++;
        }
    }
    if (v0 && c0) atomicAdd(&g_restrain[g][j0], c0);
    if (v1 && c1) atomicAdd(&g_restrain[g][j1], c1);
}

// ============================================================================
// k_correct: correct[j] = sum_{i<j, d<diam} (restrain[i] != 0)
// ============================================================================
__global__ void __launch_bounds__(256) k_correct(){
    int jc = blockIdx.x, is = blockIdx.y, g = blockIdx.z;
    int Np = g_Np[g];
    int jcbase = jc*512;
    if (jcbase >= Np) return;
    int jend = min(jcbase + 512, Np);
    int isbase = is*2048;
    if (isbase >= jend) return;

    __shared__ float4 tile[2048];
    __shared__ unsigned char nz[2048];
    int lim = min(2048, Np - isbase);
    for (int k = threadIdx.x; k < 2048; k += 256){
        if (k < lim){
            tile[k] = g_spos4[g][isbase + k];
            nz[k]   = (unsigned char)(g_restrain[g][isbase + k] != 0);
        } else {
            tile[k] = make_float4(0.f,0.f,0.f,FINF);
            nz[k]   = 0;
        }
    }
    __syncthreads();

    int tid = threadIdx.x;
    int j0 = jcbase + tid, j1 = jcbase + 256 + tid;
    bool v0 = j0 < Np, v1 = j1 < Np;
    float4 Q0 = v0 ? g_spos4[g][j0] : make_float4(0,0,0,0);
    float4 Q1 = v1 ? g_spos4[g][j1] : make_float4(0,0,0,0);
    float thr = g_thr2[g & 1];
    int c0 = 0, c1 = 0;

    if (isbase + 2048 <= jcbase){
        #pragma unroll 4
        for (int k = 0; k < 2048; k++){
            float4 f = tile[k];
            int z = nz[k];
            float ab0 = __fmaf_rn(f.z,Q0.z,__fmaf_rn(f.y,Q0.y,__fmul_rn(f.x,Q0.x)));
            float d20 = __fsub_rn(__fadd_rn(Q0.w,f.w), __fadd_rn(ab0,ab0));
            if (d20 < thr) c0 += z;
            float ab1 = __fmaf_rn(f.z,Q1.z,__fmaf_rn(f.y,Q1.y,__fmul_rn(f.x,Q1.x)));
            float d21 = __fsub_rn(__fadd_rn(Q1.w,f.w), __fadd_rn(ab1,ab1));
            if (d21 < thr) c1 += z;
        }
    } else {
        int b0 = v0 ? max(0, min(j0 - isbase, 2048)) : 0;
        int b1 = v1 ? max(0, min(j1 - isbase, 2048)) : 0;
        int e  = max(b0, b1);
        for (int k = 0; k < e; k++){
            float4 f = tile[k];
            int z = nz[k];
            float ab0 = __fmaf_rn(f.z,Q0.z,__fmaf_rn(f.y,Q0.y,__fmul_rn(f.x,Q0.x)));
            float d20 = __fsub_rn(__fadd_rn(Q0.w,f.w), __fadd_rn(ab0,ab0));
            if (k < b0 && d20 < thr) c0 += z;
            float ab1 = __fmaf_rn(f.z,Q1.z,__fmaf_rn(f.y,Q1.y,__fmul_rn(f.x,Q1.x)));
            float d21 = __fsub_rn(__fadd_rn(Q1.w,f.w), __fadd_rn(ab1,ab1));
            if (k < b1 && d21 < thr) c1 += z;
        }
    }
    if (v0 && c0) atomicAdd(&g_correct[g][j0], c0);
    if (v1 && c1) atomicAdd(&g_correct[g][j1], c1);
}

// ============================================================================
// k_nmsc: compact NMS survivors (sel = restrain==correct), stable
// ============================================================================
__global__ void __launch_bounds__(1024) k_nmsc(){
    int g = blockIdx.x, t = threadIdx.x;
    int Np = g_Np[g];
    __shared__ int sh[1024];
    int cnt = 0;
    #pragma unroll
    for (int r = 0; r < 8; r++){
        int i = t*8 + r;
        if (i < Np && g_restrain[g][i] == g_correct[g][i]) cnt++;
    }
    sh[t] = cnt; __syncthreads();
    for (int o = 1; o < 1024; o <<= 1){
        int a = 0;
        if (t >= o) a = sh[t-o];
        __syncthreads();
        sh[t] += a;
        __syncthreads();
    }
    int off = sh[t] - cnt;
    if (t == 1023) g_Ns[g] = sh[1023];
    #pragma unroll
    for (int r = 0; r < 8; r++){
        int i = t*8 + r;
        if (i < Np && g_restrain[g][i] == g_correct[g][i]){
            #pragma unroll
            for (int c = 0; c < 4; c++) g_npred[g][off][c] = g_spred[g][i][c];
            g_npos4[g][off] = g_spos4[g][i];
            off++;
        }
    }
}

// ============================================================================
// k_match: per-target min-d2 / first-occurrence argmin of sqrt row,
// tiled over p-chunks of 2048, 4 t/thread. Partials stored per chunk.
// grid (tc=16, pc=4, g=16), block 128
// ============================================================================
__global__ void __launch_bounds__(128) k_match(int u){
    int tc = blockIdx.x, pc = blockIdx.y, g = blockIdx.z;
    int Nt = g_Nt[g];
    int Npp = u ? g_Ns[g] : g_Np[g];
    int tcbase = tc*512;
    if (tcbase >= Nt) return;
    int pcbase = pc*2048;
    if (pcbase >= Npp) return;

    __shared__ float4 tile[2048];
    int lim = min(2048, Npp - pcbase);
    const float4* pp = u ? g_npos4[g] : g_ppos4[g];
    for (int k = threadIdx.x; k < lim; k += 128)
        tile[k] = pp[pcbase + k];
    __syncthreads();

    int tid = threadIdx.x;
    float tx[4], ty[4], tz[4], tb[4], d2m[4], sm[4];
    int ar[4]; bool tv[4]; int tg[4];
    #pragma unroll
    for (int q = 0; q < 4; q++){
        int t = tcbase + q*128 + tid;
        tg[q] = t; tv[q] = t < Nt;
        float4 T = tv[q] ? g_tpos4[g][t] : make_float4(0,0,0,0);
        tx[q]=T.x; ty[q]=T.y; tz[q]=T.z; tb[q]=T.w;
        d2m[q] = FINF; sm[q] = FINF; ar[q] = 0;
    }

    for (int k = 0; k < lim; k++){
        float4 f = tile[k];
        float d2v[4]; bool up[4]; bool any = false;
        #pragma unroll
        for (int q = 0; q < 4; q++){
            float ab = __fmaf_rn(f.z,tz[q],__fmaf_rn(f.y,ty[q],__fmul_rn(f.x,tx[q])));
            d2v[q] = __fsub_rn(__fadd_rn(tb[q],f.w), __fadd_rn(ab,ab));
            up[q] = d2v[q] < d2m[q];
            any = any | up[q];
        }
        if (__builtin_expect(any, 0)){
            #pragma unroll
            for (int q = 0; q < 4; q++){
                if (up[q]){
                    float s = sqrtf(fmaxf(d2v[q], 0.0f));
                    if (s < sm[q]){ sm[q] = s; ar[q] = pcbase + k; }
                    d2m[q] = d2v[q];
                }
            }
        }
    }

    #pragma unroll
    for (int q = 0; q < 4; q++){
        if (tv[q]){
            g_pd2[u][g][tg[q]][pc] = d2m[q];
            g_psm[u][g][tg[q]][pc] = sm[q];
            g_par[u][g][tg[q]][pc] = ar[q];
        }
    }
}

// ============================================================================
// k_matchred: combine p-chunk partials (ascending order preserves
// first-occurrence semantics), derive has = (min d2 < thr2)
// ============================================================================
__global__ void __launch_bounds__(256) k_matchred(){
    int g = blockIdx.y;
    int t = blockIdx.x*256 + threadIdx.x;
    int Nt = g_Nt[g];
    if (t >= Nt) return;
    float thr = g_thr2[g & 1];
    #pragma unroll
    for (int u = 0; u < 2; u++){
        int Npp = u ? g_Ns[g] : g_Np[g];
        float d2min = FINF, smin = FINF; int arg = 0;
        for (int pc = 0; pc < 4; pc++){
            if (pc*2048 < Npp){
                float s = g_psm[u][g][t][pc];
                if (s < smin){ smin = s; arg = g_par[u][g][t][pc]; }
                d2min = fminf(d2min, g_pd2[u][g][t][pc]);
            }
        }
        int has = (d2min < thr);
        if (u){ g_thasn[g][t] = has; g_targn[g][t] = arg; }
        else  { g_thas [g][t] = has; g_targ [g][t] = arg; }
    }
}

// ============================================================================
// k_matchc: compact (ti,pi) and (ti_n,pi_n)
// ============================================================================
__global__ void __launch_bounds__(1024) k_matchc(){
    int g = blockIdx.x, t = threadIdx.x;
    int Nt = g_Nt[g];
    __shared__ int s1[1024], s2[1024];
    int c1 = 0, c2 = 0;
    #pragma unroll
    for (int r = 0; r < 8; r++){
        int i = t*8 + r;
        if (i < Nt){ c1 += g_thas[g][i]; c2 += g_thasn[g][i]; }
    }
    s1[t] = c1; s2[t] = c2; __syncthreads();
    for (int o = 1; o < 1024; o <<= 1){
        int a = 0, b = 0;
        if (t >= o){ a = s1[t-o]; b = s2[t-o]; }
        __syncthreads();
        s1[t] += a; s2[t] += b;
        __syncthreads();
    }
    int o1 = s1[t] - c1, o2 = s2[t] - c2;
    if (t == 1023){ g_L[g] = s1[1023]; g_Ln[g] = s2[1023]; }
    #pragma unroll
    for (int r = 0; r < 8; r++){
        int i = t*8 + r;
        if (i < Nt){
            if (g_thas [g][i]){ g_ti [g][o1] = i; g_pi [g][o1] = g_targ [g][i]; o1++; }
            if (g_thasn[g][i]){ g_tin[g][o2] = i; g_pin[g][o2] = g_targn[g][i]; o2++; }
        }
    }
}

// ============================================================================
// k_offsets + k_write
// ============================================================================
__global__ void k_offsets(){
    if (threadIdx.x == 0 && blockIdx.x == 0){
        long long cur = 0;
        for (int g = 0; g < NG; g++){
            int Np = g_Np[g], Ns = g_Ns[g], Nt = g_Nt[g], L = g_L[g], Ln = g_Ln[g];
            long long sz[10] = { (long long)Np*4, (long long)Ns*4, (long long)Nt*4,
                                 L, L, Ln, Ln,
                                 (long long)Np*3, (long long)Ns*3, (long long)Nt*3 };
            for (int a = 0; a < 10; a++){ g_off[g][a] = cur; cur += sz[a]; }
        }
    }
}

__global__ void k_write(float* __restrict__ out){
    int g = blockIdx.x / 10, a = blockIdx.x % 10;
    int Np = g_Np[g], Ns = g_Ns[g], Nt = g_Nt[g], L = g_L[g], Ln = g_Ln[g];
    long long off = g_off[g][a];
    int n;
    switch (a){
        case 0: n = Np*4; break;
        case 1: n = Ns*4; break;
        case 2: n = Nt*4; break;
        case 3: case 4: n = L; break;
        case 5: case 6: n = Ln; break;
        case 7: n = Np*3; break;
        case 8: n = Ns*3; break;
        default: n = Nt*3; break;
    }
    const float* pp = (const float*)g_ppos4[g];
    const float* np = (const float*)g_npos4[g];
    const float* tp = (const float*)g_tpos4[g];
    for (int x = threadIdx.x; x < n; x += blockDim.x){
        float v;
        switch (a){
            case 0: v = g_pred [g][x>>2][x&3]; break;
            case 1: v = g_npred[g][x>>2][x&3]; break;
            case 2: v = g_tgt  [g][x>>2][x&3]; break;
            case 3: v = (float)g_ti [g][x]; break;
            case 4: v = (float)g_pi [g][x]; break;
            case 5: v = (float)g_tin[g][x]; break;
            case 6: v = (float)g_pin[g][x]; break;
            case 7: v = pp[(x/3)*4 + x%3]; break;
            case 8: v = np[(x/3)*4 + x%3]; break;
            default:v = tp[(x/3)*4 + x%3]; break;
        }
        out[off + x] = v;
    }
}

// ============================================================================
// Launch
// ============================================================================
extern "C" void kernel_launch(void* const* d_in, const int* in_sizes, int n_in,
                              void* d_out, int out_size){
    const float* P = (const float*)d_in[0];
    const float* T = (const float*)d_in[1];
    float* out = (float*)d_out;
    (void)in_sizes; (void)n_in; (void)out_size;

    k_init    <<<1, 32>>>();
    k_zero    <<<256, 512>>>();
    k_maskcnt <<<dim3(32,16), 256>>>(P, T);
    k_coffs   <<<1, 32>>>();
    k_scat    <<<dim3(32,16), 256>>>(P, T);
    k_sort    <<<dim3(16,16), 512>>>();
    k_restrain<<<dim3(16,4,16), 256>>>();
    k_correct <<<dim3(16,4,16), 256>>>();
    k_nmsc    <<<16, 1024>>>();
    k_match   <<<dim3(16,4,16), 128>>>(0);
    k_match   <<<dim3(16,4,16), 128>>>(1);
    k_matchred<<<dim3(32,16), 256>>>();
    k_matchc  <<<16, 1024>>>();
    k_offsets <<<1, 1>>>();
    k_write   <<<160, 256>>>(out);
}

// round 5
// speedup vs baseline: 2.2478x; 1.4245x over previous
#include <cuda_runtime.h>
#include <cstddef>

// ============================================================================
// Problem constants
// ============================================================================
#define NB   8
#define NE   2
#define NG   16
#define NC   8192
#define GMAX 8192
#define NW   (GMAX/32)     // 256 words per row
#define FINF 3.4028235e38f

static __device__ __constant__ float c_LATX = 0.78125f;  // 25/32 exact
static __device__ __constant__ float c_LATY = 0.78125f;
static __device__ __constant__ float c_LATZ = 0.375f;    // 3/8 exact

// ============================================================================
// Device scratch (allocations forbidden -> __device__ globals)
// ============================================================================
__device__ float  g_pred [NG][GMAX][4];
__device__ float4 g_ppos4[NG][GMAX];      // x,y,z,|p|^2
__device__ float  g_tgt  [NG][GMAX][4];
__device__ float4 g_tpos4[NG][GMAX];
__device__ int g_Np[NG], g_Nt[NG];
__device__ int g_ccp[NG][32], g_cct[NG][32];
__device__ int g_cop[NG][32], g_cot[NG][32];

__device__ float  g_spred[NG][GMAX][4];   // sorted ascending by prob
__device__ float4 g_spos4[NG][GMAX];
__device__ int g_restrain[NG][GMAX];
__device__ int g_correct [NG][GMAX];

// packed decision bits: bit (i&31) of g_dbits[g][i>>5][j] = (d(i,j)<diam && i<j)
__device__ unsigned g_dbits[NG][NW][GMAX];

__device__ float  g_npred[NG][GMAX][4];   // NMS survivors
__device__ float4 g_npos4[NG][GMAX];
__device__ int g_Ns[NG];

// match partials per p-chunk (4 chunks of 2048), [0]=full, [1]=nms
__device__ float g_pd2[2][NG][GMAX][4];
__device__ float g_psm[2][NG][GMAX][4];
__device__ int   g_par[2][NG][GMAX][4];

__device__ int g_ti[NG][GMAX], g_pi[NG][GMAX];
__device__ int g_tin[NG][GMAX], g_pin[NG][GMAX];
__device__ int g_L[NG], g_Ln[NG];

__device__ long long g_off[NG][10];
__device__ float g_thr2[NE];

// ============================================================================
// Rounding-exact helpers (validated rel_err==0.0)
// ============================================================================
__device__ __forceinline__ float nrm3(float x,float y,float z){
    return __fadd_rn(__fadd_rn(__fmul_rn(x,x),__fmul_rn(y,y)),__fmul_rn(z,z));
}

// ============================================================================
// k_zero: clear restrain accumulators + compute d2 thresholds (fused init)
// ============================================================================
__global__ void __launch_bounds__(512) k_zero(){
    int i = blockIdx.x*512 + threadIdx.x;
    if (i < NG*GMAX) ((int*)g_restrain)[i] = 0;
    if (blockIdx.x == 0 && threadIdx.x < NE){
        int e = threadIdx.x;
        float diam = (e==0) ? (float)(0.74*1.4) : (float)(0.528*1.4);
        float d2 = diam*diam;
        unsigned lo = __float_as_uint(d2*0.5f);
        unsigned hi = __float_as_uint(d2*2.0f);
        while (lo + 1u < hi){
            unsigned mid = lo + ((hi - lo) >> 1);
            if (sqrtf(__uint_as_float(mid)) >= diam) hi = mid; else lo = mid;
        }
        g_thr2[e] = __uint_as_float(hi);
    }
}

// ============================================================================
// Compaction phase (count -> prefix -> scatter)
// ============================================================================
__global__ void __launch_bounds__(256) k_maskcnt(const float* __restrict__ P,
                                                 const float* __restrict__ T){
    int chunk = blockIdx.x, g = blockIdx.y, b = g >> 1, e = g & 1;
    int c = chunk*256 + threadIdx.x;
    size_t base = (((size_t)(b*NC + c))*2 + (size_t)e)*4;
    int mp = P[base+3] > 0.5f;
    int mt = T[base+3] > 0.5f;
    int cp = __syncthreads_count(mp);
    int ct = __syncthreads_count(mt);
    if (threadIdx.x == 0){ g_ccp[g][chunk] = cp; g_cct[g][chunk] = ct; }
}

__global__ void k_coffs(){
    int g = threadIdx.x;
    if (g < NG){
        int op = 0, ot = 0;
        for (int c = 0; c < 32; c++){
            g_cop[g][c] = op; op += g_ccp[g][c];
            g_cot[g][c] = ot; ot += g_cct[g][c];
        }
        g_Np[g] = op; g_Nt[g] = ot;
    }
}

__global__ void __launch_bounds__(256) k_scat(const float* __restrict__ P,
                                              const float* __restrict__ T){
    int chunk = blockIdx.x, g = blockIdx.y, b = g >> 1, e = g & 1;
    int tid = threadIdx.x;
    int c = chunk*256 + tid;
    size_t idx4 = ((size_t)(b*NC + c))*2 + (size_t)e;
    float4 pv = ((const float4*)P)[idx4];
    float4 tv = ((const float4*)T)[idx4];
    int mp = pv.w > 0.5f;
    int mt = tv.w > 0.5f;

    unsigned bp = __ballot_sync(0xffffffffu, mp);
    unsigned bt = __ballot_sync(0xffffffffu, mt);
    int lane = tid & 31, w = tid >> 5;
    __shared__ int wpo[8], wto[8], wpc[8], wtc[8];
    if (lane == 0){ wpc[w] = __popc(bp); wtc[w] = __popc(bt); }
    __syncthreads();
    if (tid == 0){
        int a = 0, b2 = 0;
        for (int k = 0; k < 8; k++){ wpo[k] = a; a += wpc[k]; wto[k] = b2; b2 += wtc[k]; }
    }
    __syncthreads();

    int ci = c >> 8, cj = (c >> 3) & 31, ck = c & 7;
    unsigned ltm = (1u << lane) - 1u;
    if (mp){
        int o = g_cop[g][chunk] + wpo[w] + __popc(bp & ltm);
        g_pred[g][o][0] = pv.x; g_pred[g][o][1] = pv.y;
        g_pred[g][o][2] = pv.z; g_pred[g][o][3] = pv.w;
        float px = __fmul_rn(__fadd_rn(pv.x,(float)ci), c_LATX);
        float py = __fmul_rn(__fadd_rn(pv.y,(float)cj), c_LATY);
        float pz = __fmul_rn(__fadd_rn(pv.z,(float)ck), c_LATZ);
        g_ppos4[g][o] = make_float4(px,py,pz, nrm3(px,py,pz));
    }
    if (mt){
        int o = g_cot[g][chunk] + wto[w] + __popc(bt & ltm);
        g_tgt[g][o][0] = tv.x; g_tgt[g][o][1] = tv.y;
        g_tgt[g][o][2] = tv.z; g_tgt[g][o][3] = tv.w;
        float px = __fmul_rn(__fadd_rn(tv.x,(float)ci), c_LATX);
        float py = __fmul_rn(__fadd_rn(tv.y,(float)cj), c_LATY);
        float pz = __fmul_rn(__fadd_rn(tv.z,(float)ck), c_LATZ);
        g_tpos4[g][o] = make_float4(px,py,pz, nrm3(px,py,pz));
    }
}

// ============================================================================
// k_sort: stable ascending rank-sort, 2 i's per thread (shared broadcast)
// grid (ic=8 chunks of 1024, g=16), block 512
// ============================================================================
__global__ void __launch_bounds__(512) k_sort(){
    int ic = blockIdx.x, g = blockIdx.y;
    int Np = g_Np[g];
    __shared__ float sp[GMAX];
    for (int j = threadIdx.x; j < GMAX; j += 512)
        sp[j] = (j < Np) ? g_pred[g][j][3] : FINF;
    __syncthreads();
    int i0 = ic*1024 + threadIdx.x;
    int i1 = i0 + 512;
    if (i0 >= Np) return;
    bool v1 = i1 < Np;
    float p0 = sp[i0];
    float p1 = v1 ? sp[i1] : FINF;
    int r0 = 0, r1 = 0;
    // segment [0, i0): both use <=
    #pragma unroll 4
    for (int j = 0; j < i0; j++){
        float u = sp[j];
        r0 += (u <= p0); r1 += (u <= p1);
    }
    // j = i0 counts for r1 (j < i1)
    r1 += (p0 <= p1);
    // segment (i0, i1): r0 strict, r1 <=
    int i1c = v1 ? i1 : Np;
    #pragma unroll 4
    for (int j = i0+1; j < i1c; j++){
        float u = sp[j];
        r0 += (u < p0); r1 += (u <= p1);
    }
    // j = i1 counts for r0 (strict)
    if (v1) r0 += (p1 < p0);
    // segment (i1, Np): both strict
    #pragma unroll 4
    for (int j = i1c+1; j < Np; j++){
        float u = sp[j];
        r0 += (u < p0); r1 += (u < p1);
    }
    {
        g_spred[g][r0][0] = g_pred[g][i0][0];
        g_spred[g][r0][1] = g_pred[g][i0][1];
        g_spred[g][r0][2] = g_pred[g][i0][2];
        g_spred[g][r0][3] = g_pred[g][i0][3];
        g_spos4[g][r0] = g_ppos4[g][i0];
    }
    if (v1){
        g_spred[g][r1][0] = g_pred[g][i1][0];
        g_spred[g][r1][1] = g_pred[g][i1][1];
        g_spred[g][r1][2] = g_pred[g][i1][2];
        g_spred[g][r1][3] = g_pred[g][i1][3];
        g_spos4[g][r1] = g_ppos4[g][i1];
    }
}

// ============================================================================
// k_restrain: restrain[j] = #{i<j : d(i,j)<diam}, AND stores the decision
// bits packed 32/word into g_dbits[g][w][j] (boundary words pre-masked i<j).
// grid (jc=16, is=4, g=16), block 256, 2 j's/thread
// ============================================================================
__global__ void __launch_bounds__(256) k_restrain(){
    int jc = blockIdx.x, is = blockIdx.y, g = blockIdx.z;
    int Np = g_Np[g];
    int jcbase = jc*512;
    if (jcbase >= Np) return;
    int jend = min(jcbase + 512, Np);
    int isbase = is*2048;
    if (isbase >= jend) return;
    int wbase = isbase >> 5;

    __shared__ float4 tile[2048];
    int lim = min(2048, Np - isbase);
    for (int k = threadIdx.x; k < 2048; k += 256)
        tile[k] = (k < lim) ? g_spos4[g][isbase + k] : make_float4(0.f,0.f,0.f,FINF);
    __syncthreads();

    int tid = threadIdx.x;
    int j0 = jcbase + tid, j1 = jcbase + 256 + tid;
    bool v0 = j0 < Np, v1 = j1 < Np;
    float4 Q0 = v0 ? g_spos4[g][j0] : make_float4(0,0,0,0);
    float4 Q1 = v1 ? g_spos4[g][j1] : make_float4(0,0,0,0);
    float thr = g_thr2[g & 1];
    int c0 = 0, c1 = 0;
    // tile-relative i<j limits (0 if invalid j)
    int lim0 = v0 ? max(0, min(j0 - isbase, 2048)) : 0;
    int lim1 = v1 ? max(0, min(j1 - isbase, 2048)) : 0;
    bool full = (isbase + 2048 <= jcbase);   // whole tile strictly below all j's

    for (int wl = 0; wl < 64; wl++){
        unsigned b0 = 0, b1 = 0;
        int kb = wl << 5;
        #pragma unroll
        for (int b = 0; b < 32; b++){
            float4 f = tile[kb + b];
            float ab0 = __fmaf_rn(f.z,Q0.z,__fmaf_rn(f.y,Q0.y,__fmul_rn(f.x,Q0.x)));
            float d20 = __fsub_rn(__fadd_rn(Q0.w,f.w), __fadd_rn(ab0,ab0));
            if (d20 < thr) b0 |= (1u << b);
            float ab1 = __fmaf_rn(f.z,Q1.z,__fmaf_rn(f.y,Q1.y,__fmul_rn(f.x,Q1.x)));
            float d21 = __fsub_rn(__fadd_rn(Q1.w,f.w), __fadd_rn(ab1,ab1));
            if (d21 < thr) b1 |= (1u << b);
        }
        if (full){
            c0 += __popc(b0); c1 += __popc(b1);
            if (v0) g_dbits[g][wbase + wl][j0] = b0;
            if (v1) g_dbits[g][wbase + wl][j1] = b1;
        } else {
            int r0 = lim0 - kb;   // valid bit count in this word for j0
            int r1 = lim1 - kb;
            unsigned m0 = (r0 >= 32) ? 0xffffffffu : ((r0 > 0) ? ((1u << r0) - 1u) : 0u);
            unsigned m1 = (r1 >= 32) ? 0xffffffffu : ((r1 > 0) ? ((1u << r1) - 1u) : 0u);
            b0 &= m0; b1 &= m1;
            c0 += __popc(b0); c1 += __popc(b1);
            if (m0) g_dbits[g][wbase + wl][j0] = b0;
            if (m1) g_dbits[g][wbase + wl][j1] = b1;
        }
    }
    if (v0 && c0) atomicAdd(&g_restrain[g][j0], c0);
    if (v1 && c1) atomicAdd(&g_restrain[g][j1], c1);
}

// ============================================================================
// k_correct: correct[j] = sum over stored bits AND (restrain[i]!=0), via
// popcount of word-AND. grid (jc=16, g=16), block 512, 1 j/thread.
// ============================================================================
__global__ void __launch_bounds__(512) k_correct(){
    int g = blockIdx.y;
    int Np = g_Np[g];
    int tid = threadIdx.x;
    __shared__ unsigned nzw[NW];
    int lane = tid & 31, w = tid >> 5;
    #pragma unroll
    for (int pass = 0; pass < 16; pass++){
        int i = pass*512 + tid;
        int pred = (i < Np) && (g_restrain[g][i] != 0);
        unsigned bw = __ballot_sync(0xffffffffu, pred);
        if (lane == 0) nzw[pass*16 + w] = bw;
    }
    __syncthreads();
    int j = blockIdx.x*512 + tid;
    if (j >= Np) return;
    int nw = (j + 31) >> 5;     // words covering i in [0, j)
    int c = 0;
    #pragma unroll 4
    for (int w2 = 0; w2 < nw; w2++)
        c += __popc(g_dbits[g][w2][j] & nzw[w2]);
    g_correct[g][j] = c;
}

// ============================================================================
// k_nmsc: compact NMS survivors (sel = restrain==correct), stable
// ============================================================================
__global__ void __launch_bounds__(1024) k_nmsc(){
    int g = blockIdx.x, t = threadIdx.x;
    int Np = g_Np[g];
    __shared__ int sh[1024];
    int cnt = 0;
    #pragma unroll
    for (int r = 0; r < 8; r++){
        int i = t*8 + r;
        if (i < Np && g_restrain[g][i] == g_correct[g][i]) cnt++;
    }
    sh[t] = cnt; __syncthreads();
    for (int o = 1; o < 1024; o <<= 1){
        int a = 0;
        if (t >= o) a = sh[t-o];
        __syncthreads();
        sh[t] += a;
        __syncthreads();
    }
    int off = sh[t] - cnt;
    if (t == 1023) g_Ns[g] = sh[1023];
    #pragma unroll
    for (int r = 0; r < 8; r++){
        int i = t*8 + r;
        if (i < Np && g_restrain[g][i] == g_correct[g][i]){
            #pragma unroll
            for (int c = 0; c < 4; c++) g_npred[g][off][c] = g_spred[g][i][c];
            g_npos4[g][off] = g_spos4[g][i];
            off++;
        }
    }
}

// ============================================================================
// k_match: both full (u=0) and NMS (u=1) matches in one launch.
// blockIdx.y in [0,8): u = y>>2, pc = y&3. 4 t/thread, p-tiles of 2048.
// ============================================================================
__global__ void __launch_bounds__(128) k_match(){
    int tc = blockIdx.x, g = blockIdx.z;
    int u  = blockIdx.y >> 2, pc = blockIdx.y & 3;
    int Nt = g_Nt[g];
    int Npp = u ? g_Ns[g] : g_Np[g];
    int tcbase = tc*512;
    if (tcbase >= Nt) return;
    int pcbase = pc*2048;
    if (pcbase >= Npp) return;

    __shared__ float4 tile[2048];
    int lim = min(2048, Npp - pcbase);
    const float4* pp = u ? g_npos4[g] : g_ppos4[g];
    for (int k = threadIdx.x; k < lim; k += 128)
        tile[k] = pp[pcbase + k];
    __syncthreads();

    int tid = threadIdx.x;
    float tx[4], ty[4], tz[4], tb[4], d2m[4], sm[4];
    int ar[4]; bool tv[4]; int tg[4];
    #pragma unroll
    for (int q = 0; q < 4; q++){
        int t = tcbase + q*128 + tid;
        tg[q] = t; tv[q] = t < Nt;
        float4 T = tv[q] ? g_tpos4[g][t] : make_float4(0,0,0,0);
        tx[q]=T.x; ty[q]=T.y; tz[q]=T.z; tb[q]=T.w;
        d2m[q] = FINF; sm[q] = FINF; ar[q] = 0;
    }

    for (int k = 0; k < lim; k++){
        float4 f = tile[k];
        float d2v[4]; bool up[4]; bool any = false;
        #pragma unroll
        for (int q = 0; q < 4; q++){
            float ab = __fmaf_rn(f.z,tz[q],__fmaf_rn(f.y,ty[q],__fmul_rn(f.x,tx[q])));
            d2v[q] = __fsub_rn(__fadd_rn(tb[q],f.w), __fadd_rn(ab,ab));
            up[q] = d2v[q] < d2m[q];
            any = any | up[q];
        }
        if (__builtin_expect(any, 0)){
            #pragma unroll
            for (int q = 0; q < 4; q++){
                if (up[q]){
                    float s = sqrtf(fmaxf(d2v[q], 0.0f));
                    if (s < sm[q]){ sm[q] = s; ar[q] = pcbase + k; }
                    d2m[q] = d2v[q];
                }
            }
        }
    }

    #pragma unroll
    for (int q = 0; q < 4; q++){
        if (tv[q]){
            g_pd2[u][g][tg[q]][pc] = d2m[q];
            g_psm[u][g][tg[q]][pc] = sm[q];
            g_par[u][g][tg[q]][pc] = ar[q];
        }
    }
}

// ============================================================================
// k_matchc: inline chunk-combine (ascending pc preserves first-occurrence
// argmin; has = min d2 < thr2) + stable compaction of (ti,pi)/(ti_n,pi_n)
// ============================================================================
__global__ void __launch_bounds__(1024) k_matchc(){
    int g = blockIdx.x, t = threadIdx.x;
    int Nt = g_Nt[g];
    float thr = g_thr2[g & 1];
    int NpF = g_Np[g], NpN = g_Ns[g];

    int has0[8], arg0[8], has1[8], arg1[8];
    int c1 = 0, c2 = 0;
    #pragma unroll
    for (int r = 0; r < 8; r++){
        int i = t*8 + r;
        has0[r] = has1[r] = 0; arg0[r] = arg1[r] = 0;
        if (i < Nt){
            // u = 0 (full)
            {
                float d2min = FINF, smin = FINF; int arg = 0;
                for (int pc = 0; pc < 4; pc++){
                    if (pc*2048 < NpF){
                        float s = g_psm[0][g][i][pc];
                        if (s < smin){ smin = s; arg = g_par[0][g][i][pc]; }
                        d2min = fminf(d2min, g_pd2[0][g][i][pc]);
                    }
                }
                has0[r] = (d2min < thr); arg0[r] = arg;
            }
            // u = 1 (nms)
            {
                float d2min = FINF, smin = FINF; int arg = 0;
                for (int pc = 0; pc < 4; pc++){
                    if (pc*2048 < NpN){
                        float s = g_psm[1][g][i][pc];
                        if (s < smin){ smin = s; arg = g_par[1][g][i][pc]; }
                        d2min = fminf(d2min, g_pd2[1][g][i][pc]);
                    }
                }
                has1[r] = (d2min < thr); arg1[r] = arg;
            }
            c1 += has0[r]; c2 += has1[r];
        }
    }

    __shared__ int s1[1024], s2[1024];
    s1[t] = c1; s2[t] = c2; __syncthreads();
    for (int o = 1; o < 1024; o <<= 1){
        int a = 0, b = 0;
        if (t >= o){ a = s1[t-o]; b = s2[t-o]; }
        __syncthreads();
        s1[t] += a; s2[t] += b;
        __syncthreads();
    }
    int o1 = s1[t] - c1, o2 = s2[t] - c2;
    if (t == 1023){ g_L[g] = s1[1023]; g_Ln[g] = s2[1023]; }
    #pragma unroll
    for (int r = 0; r < 8; r++){
        int i = t*8 + r;
        if (i < Nt){
            if (has0[r]){ g_ti [g][o1] = i; g_pi [g][o1] = arg0[r]; o1++; }
            if (has1[r]){ g_tin[g][o2] = i; g_pin[g][o2] = arg1[r]; o2++; }
        }
    }
}

// ============================================================================
// k_offsets + k_write
// ============================================================================
__global__ void k_offsets(){
    if (threadIdx.x == 0 && blockIdx.x == 0){
        long long cur = 0;
        for (int g = 0; g < NG; g++){
            int Np = g_Np[g], Ns = g_Ns[g], Nt = g_Nt[g], L = g_L[g], Ln = g_Ln[g];
            long long sz[10] = { (long long)Np*4, (long long)Ns*4, (long long)Nt*4,
                                 L, L, Ln, Ln,
                                 (long long)Np*3, (long long)Ns*3, (long long)Nt*3 };
            for (int a = 0; a < 10; a++){ g_off[g][a] = cur; cur += sz[a]; }
        }
    }
}

__global__ void k_write(float* __restrict__ out){
    int g = blockIdx.x / 10, a = blockIdx.x % 10;
    int Np = g_Np[g], Ns = g_Ns[g], Nt = g_Nt[g], L = g_L[g], Ln = g_Ln[g];
    long long off = g_off[g][a];
    int n;
    switch (a){
        case 0: n = Np*4; break;
        case 1: n = Ns*4; break;
        case 2: n = Nt*4; break;
        case 3: case 4: n = L; break;
        case 5: case 6: n = Ln; break;
        case 7: n = Np*3; break;
        case 8: n = Ns*3; break;
        default: n = Nt*3; break;
    }
    const float* pp = (const float*)g_ppos4[g];
    const float* np = (const float*)g_npos4[g];
    const float* tp = (const float*)g_tpos4[g];
    for (int x = threadIdx.x; x < n; x += blockDim.x){
        float v;
        switch (a){
            case 0: v = g_pred [g][x>>2][x&3]; break;
            case 1: v = g_npred[g][x>>2][x&3]; break;
            case 2: v = g_tgt  [g][x>>2][x&3]; break;
            case 3: v = (float)g_ti [g][x]; break;
            case 4: v = (float)g_pi [g][x]; break;
            case 5: v = (float)g_tin[g][x]; break;
            case 6: v = (float)g_pin[g][x]; break;
            case 7: v = pp[(x/3)*4 + x%3]; break;
            case 8: v = np[(x/3)*4 + x%3]; break;
            default:v = tp[(x/3)*4 + x%3]; break;
        }
        out[off + x] = v;
    }
}

// ============================================================================
// Launch
// ============================================================================
extern "C" void kernel_launch(void* const* d_in, const int* in_sizes, int n_in,
                              void* d_out, int out_size){
    const float* P = (const float*)d_in[0];
    const float* T = (const float*)d_in[1];
    float* out = (float*)d_out;
    (void)in_sizes; (void)n_in; (void)out_size;

    k_zero    <<<256, 512>>>();
    k_maskcnt <<<dim3(32,16), 256>>>(P, T);
    k_coffs   <<<1, 32>>>();
    k_scat    <<<dim3(32,16), 256>>>(P, T);
    k_sort    <<<dim3(8,16), 512>>>();
    k_restrain<<<dim3(16,4,16), 256>>>();
    k_correct <<<dim3(16,16), 512>>>();
    k_nmsc    <<<16, 1024>>>();
    k_match   <<<dim3(16,8,16), 128>>>();
    k_matchc  <<<16, 1024>>>();
    k_offsets <<<1, 1>>>();
    k_write   <<<160, 256>>>(out);
}

// round 6
// speedup vs baseline: 2.9228x; 1.3003x over previous
#include <cuda_runtime.h>
#include <cstddef>

// ============================================================================
// Problem constants
// ============================================================================
#define NB   8
#define NE   2
#define NG   16
#define NC   8192
#define GMAX 8192
#define NW   (GMAX/32)     // 256 words per row
#define NPC  8             // match p-chunks of 1024
#define FINF 3.4028235e38f

static __device__ __constant__ float c_LATX = 0.78125f;  // 25/32 exact
static __device__ __constant__ float c_LATY = 0.78125f;
static __device__ __constant__ float c_LATZ = 0.375f;    // 3/8 exact

// ============================================================================
// Device scratch (allocations forbidden -> __device__ globals)
// ============================================================================
__device__ float  g_pred [NG][GMAX][4];
__device__ float4 g_ppos4[NG][GMAX];      // x,y,z,|p|^2
__device__ float  g_tgt  [NG][GMAX][4];
__device__ float4 g_tpos4[NG][GMAX];
__device__ int g_Np[NG], g_Nt[NG];
__device__ int g_ccp[NG][32], g_cct[NG][32];
__device__ int g_cop[NG][32], g_cot[NG][32];

__device__ float  g_spred[NG][GMAX][4];   // sorted ascending by prob
__device__ float4 g_spos4[NG][GMAX];
__device__ int g_restrain[NG][GMAX];
__device__ int g_correct [NG][GMAX];

// packed decision bits: bit (i&31) of g_dbits[g][i>>5][j] = (d(i,j)<diam && i<j)
__device__ unsigned g_dbits[NG][NW][GMAX];

__device__ float  g_npred[NG][GMAX][4];   // NMS survivors
__device__ float4 g_npos4[NG][GMAX];
__device__ int g_Ns[NG];

// match partials per p-chunk (8 chunks of 1024), [0]=full, [1]=nms
__device__ float g_pd2[2][NG][GMAX][NPC];
__device__ float g_psm[2][NG][GMAX][NPC];
__device__ int   g_par[2][NG][GMAX][NPC];

__device__ int g_ti[NG][GMAX], g_pi[NG][GMAX];
__device__ int g_tin[NG][GMAX], g_pin[NG][GMAX];
__device__ int g_L[NG], g_Ln[NG];

__device__ float g_thr2[NE];

// ============================================================================
// Rounding-exact helpers (validated rel_err==0.0)
// ============================================================================
__device__ __forceinline__ float nrm3(float x,float y,float z){
    return __fadd_rn(__fadd_rn(__fmul_rn(x,x),__fmul_rn(y,y)),__fmul_rn(z,z));
}

// ============================================================================
// k_maskcnt: threshold-count per 256-cell chunk + zero restrain accumulators
// + bit-search d2 thresholds (all fused)
// ============================================================================
__global__ void __launch_bounds__(256) k_maskcnt(const float* __restrict__ P,
                                                 const float* __restrict__ T){
    int chunk = blockIdx.x, g = blockIdx.y, b = g >> 1, e = g & 1;
    int tid = threadIdx.x;
    // zero restrain/correct accumulator slice (512 blocks x 256 = NG*GMAX)
    int zi = (g*32 + chunk)*256 + tid;
    ((int*)g_restrain)[zi] = 0;
    // thr2 bit-search (one block, 2 threads)
    if (chunk == 0 && g == 0 && tid < NE){
        float diam = (tid==0) ? (float)(0.74*1.4) : (float)(0.528*1.4);
        float d2 = diam*diam;
        unsigned lo = __float_as_uint(d2*0.5f);
        unsigned hi = __float_as_uint(d2*2.0f);
        while (lo + 1u < hi){
            unsigned mid = lo + ((hi - lo) >> 1);
            if (sqrtf(__uint_as_float(mid)) >= diam) hi = mid; else lo = mid;
        }
        g_thr2[tid] = __uint_as_float(hi);
    }
    int c = chunk*256 + tid;
    size_t base = (((size_t)(b*NC + c))*2 + (size_t)e)*4;
    int mp = P[base+3] > 0.5f;
    int mt = T[base+3] > 0.5f;
    int cp = __syncthreads_count(mp);
    int ct = __syncthreads_count(mt);
    if (tid == 0){ g_ccp[g][chunk] = cp; g_cct[g][chunk] = ct; }
}

__global__ void k_coffs(){
    int g = threadIdx.x;
    if (g < NG){
        int op = 0, ot = 0;
        for (int c = 0; c < 32; c++){
            g_cop[g][c] = op; op += g_ccp[g][c];
            g_cot[g][c] = ot; ot += g_cct[g][c];
        }
        g_Np[g] = op; g_Nt[g] = ot;
    }
}

__global__ void __launch_bounds__(256) k_scat(const float* __restrict__ P,
                                              const float* __restrict__ T){
    int chunk = blockIdx.x, g = blockIdx.y, b = g >> 1, e = g & 1;
    int tid = threadIdx.x;
    int c = chunk*256 + tid;
    size_t idx4 = ((size_t)(b*NC + c))*2 + (size_t)e;
    float4 pv = ((const float4*)P)[idx4];
    float4 tv = ((const float4*)T)[idx4];
    int mp = pv.w > 0.5f;
    int mt = tv.w > 0.5f;

    unsigned bp = __ballot_sync(0xffffffffu, mp);
    unsigned bt = __ballot_sync(0xffffffffu, mt);
    int lane = tid & 31, w = tid >> 5;
    __shared__ int wpo[8], wto[8], wpc[8], wtc[8];
    if (lane == 0){ wpc[w] = __popc(bp); wtc[w] = __popc(bt); }
    __syncthreads();
    if (tid == 0){
        int a = 0, b2 = 0;
        for (int k = 0; k < 8; k++){ wpo[k] = a; a += wpc[k]; wto[k] = b2; b2 += wtc[k]; }
    }
    __syncthreads();

    int ci = c >> 8, cj = (c >> 3) & 31, ck = c & 7;
    unsigned ltm = (1u << lane) - 1u;
    if (mp){
        int o = g_cop[g][chunk] + wpo[w] + __popc(bp & ltm);
        g_pred[g][o][0] = pv.x; g_pred[g][o][1] = pv.y;
        g_pred[g][o][2] = pv.z; g_pred[g][o][3] = pv.w;
        float px = __fmul_rn(__fadd_rn(pv.x,(float)ci), c_LATX);
        float py = __fmul_rn(__fadd_rn(pv.y,(float)cj), c_LATY);
        float pz = __fmul_rn(__fadd_rn(pv.z,(float)ck), c_LATZ);
        g_ppos4[g][o] = make_float4(px,py,pz, nrm3(px,py,pz));
    }
    if (mt){
        int o = g_cot[g][chunk] + wto[w] + __popc(bt & ltm);
        g_tgt[g][o][0] = tv.x; g_tgt[g][o][1] = tv.y;
        g_tgt[g][o][2] = tv.z; g_tgt[g][o][3] = tv.w;
        float px = __fmul_rn(__fadd_rn(tv.x,(float)ci), c_LATX);
        float py = __fmul_rn(__fadd_rn(tv.y,(float)cj), c_LATY);
        float pz = __fmul_rn(__fadd_rn(tv.z,(float)ck), c_LATZ);
        g_tpos4[g][o] = make_float4(px,py,pz, nrm3(px,py,pz));
    }
}

// ============================================================================
// k_sort: stable ascending rank-sort, 2 i's per thread (shared broadcast)
// ============================================================================
__global__ void __launch_bounds__(512) k_sort(){
    int ic = blockIdx.x, g = blockIdx.y;
    int Np = g_Np[g];
    __shared__ float sp[GMAX];
    for (int j = threadIdx.x; j < GMAX; j += 512)
        sp[j] = (j < Np) ? g_pred[g][j][3] : FINF;
    __syncthreads();
    int i0 = ic*1024 + threadIdx.x;
    int i1 = i0 + 512;
    if (i0 >= Np) return;
    bool v1 = i1 < Np;
    float p0 = sp[i0];
    float p1 = v1 ? sp[i1] : FINF;
    int r0 = 0, r1 = 0;
    #pragma unroll 4
    for (int j = 0; j < i0; j++){
        float u = sp[j];
        r0 += (u <= p0); r1 += (u <= p1);
    }
    r1 += (p0 <= p1);
    int i1c = v1 ? i1 : Np;
    #pragma unroll 4
    for (int j = i0+1; j < i1c; j++){
        float u = sp[j];
        r0 += (u < p0); r1 += (u <= p1);
    }
    if (v1) r0 += (p1 < p0);
    #pragma unroll 4
    for (int j = i1c+1; j < Np; j++){
        float u = sp[j];
        r0 += (u < p0); r1 += (u < p1);
    }
    {
        g_spred[g][r0][0] = g_pred[g][i0][0];
        g_spred[g][r0][1] = g_pred[g][i0][1];
        g_spred[g][r0][2] = g_pred[g][i0][2];
        g_spred[g][r0][3] = g_pred[g][i0][3];
        g_spos4[g][r0] = g_ppos4[g][i0];
    }
    if (v1){
        g_spred[g][r1][0] = g_pred[g][i1][0];
        g_spred[g][r1][1] = g_pred[g][i1][1];
        g_spred[g][r1][2] = g_pred[g][i1][2];
        g_spred[g][r1][3] = g_pred[g][i1][3];
        g_spos4[g][r1] = g_ppos4[g][i1];
    }
}

// ============================================================================
// k_restrain: restrain[j] = #{i<j : d(i,j)<diam}, stores decision bits.
// i-tiles of 1024; word loop bounded to the triangle (wcnt).
// grid (jc=16, is=8, g=16), block 256, 2 j's/thread
// ============================================================================
__global__ void __launch_bounds__(256) k_restrain(){
    int jc = blockIdx.x, is = blockIdx.y, g = blockIdx.z;
    int Np = g_Np[g];
    int jcbase = jc*512;
    if (jcbase >= Np) return;
    int jend = min(jcbase + 512, Np);
    int isbase = is*1024;
    if (isbase >= jend) return;
    int wbase = isbase >> 5;

    __shared__ float4 tile[1024];
    int lim = min(1024, Np - isbase);
    for (int k = threadIdx.x; k < 1024; k += 256)
        tile[k] = (k < lim) ? g_spos4[g][isbase + k] : make_float4(0.f,0.f,0.f,FINF);
    __syncthreads();

    int tid = threadIdx.x;
    int j0 = jcbase + tid, j1 = jcbase + 256 + tid;
    bool v0 = j0 < Np, v1 = j1 < Np;
    float4 Q0 = v0 ? g_spos4[g][j0] : make_float4(0,0,0,0);
    float4 Q1 = v1 ? g_spos4[g][j1] : make_float4(0,0,0,0);
    float thr = g_thr2[g & 1];
    int c0 = 0, c1 = 0;
    int lim0 = v0 ? max(0, min(j0 - isbase, 1024)) : 0;   // tile-relative i<j bound
    int lim1 = v1 ? max(0, min(j1 - isbase, 1024)) : 0;
    bool full = (isbase + 1024 <= jcbase);
    // only words that can hold i < jend matter (others never read nor counted)
    int ilim = min(lim, jend - isbase);
    int wcnt = (ilim + 31) >> 5;

    for (int wl = 0; wl < wcnt; wl++){
        unsigned b0 = 0, b1 = 0;
        int kb = wl << 5;
        #pragma unroll
        for (int b = 0; b < 32; b++){
            float4 f = tile[kb + b];
            float ab0 = __fmaf_rn(f.z,Q0.z,__fmaf_rn(f.y,Q0.y,__fmul_rn(f.x,Q0.x)));
            float d20 = __fsub_rn(__fadd_rn(Q0.w,f.w), __fadd_rn(ab0,ab0));
            if (d20 < thr) b0 |= (1u << b);
            float ab1 = __fmaf_rn(f.z,Q1.z,__fmaf_rn(f.y,Q1.y,__fmul_rn(f.x,Q1.x)));
            float d21 = __fsub_rn(__fadd_rn(Q1.w,f.w), __fadd_rn(ab1,ab1));
            if (d21 < thr) b1 |= (1u << b);
        }
        if (full){
            c0 += __popc(b0); c1 += __popc(b1);
            if (v0) g_dbits[g][wbase + wl][j0] = b0;
            if (v1) g_dbits[g][wbase + wl][j1] = b1;
        } else {
            int r0 = lim0 - kb;
            int r1 = lim1 - kb;
            unsigned m0 = (r0 >= 32) ? 0xffffffffu : ((r0 > 0) ? ((1u << r0) - 1u) : 0u);
            unsigned m1 = (r1 >= 32) ? 0xffffffffu : ((r1 > 0) ? ((1u << r1) - 1u) : 0u);
            b0 &= m0; b1 &= m1;
            c0 += __popc(b0); c1 += __popc(b1);
            if (m0) g_dbits[g][wbase + wl][j0] = b0;
            if (m1) g_dbits[g][wbase + wl][j1] = b1;
        }
    }
    if (v0 && c0) atomicAdd(&g_restrain[g][j0], c0);
    if (v1 && c1) atomicAdd(&g_restrain[g][j1], c1);
}

// ============================================================================
// k_correct: correct[j] = popc(dbits[w][j] & nz_word[w]) over words below j
// ============================================================================
__global__ void __launch_bounds__(512) k_correct(){
    int g = blockIdx.y;
    int Np = g_Np[g];
    int tid = threadIdx.x;
    __shared__ unsigned nzw[NW];
    int lane = tid & 31, w = tid >> 5;
    #pragma unroll
    for (int pass = 0; pass < 16; pass++){
        int i = pass*512 + tid;
        int pred = (i < Np) && (g_restrain[g][i] != 0);
        unsigned bw = __ballot_sync(0xffffffffu, pred);
        if (lane == 0) nzw[pass*16 + w] = bw;
    }
    __syncthreads();
    int j = blockIdx.x*512 + tid;
    if (j >= Np) return;
    int nw = (j + 31) >> 5;
    int c = 0;
    #pragma unroll 4
    for (int w2 = 0; w2 < nw; w2++)
        c += __popc(g_dbits[g][w2][j] & nzw[w2]);
    g_correct[g][j] = c;
}

// ============================================================================
// k_nmsc: compact NMS survivors (sel = restrain==correct), stable
// ============================================================================
__global__ void __launch_bounds__(1024) k_nmsc(){
    int g = blockIdx.x, t = threadIdx.x;
    int Np = g_Np[g];
    __shared__ int sh[1024];
    int cnt = 0;
    #pragma unroll
    for (int r = 0; r < 8; r++){
        int i = t*8 + r;
        if (i < Np && g_restrain[g][i] == g_correct[g][i]) cnt++;
    }
    sh[t] = cnt; __syncthreads();
    for (int o = 1; o < 1024; o <<= 1){
        int a = 0;
        if (t >= o) a = sh[t-o];
        __syncthreads();
        sh[t] += a;
        __syncthreads();
    }
    int off = sh[t] - cnt;
    if (t == 1023) g_Ns[g] = sh[1023];
    #pragma unroll
    for (int r = 0; r < 8; r++){
        int i = t*8 + r;
        if (i < Np && g_restrain[g][i] == g_correct[g][i]){
            #pragma unroll
            for (int c = 0; c < 4; c++) g_npred[g][off][c] = g_spred[g][i][c];
            g_npos4[g][off] = g_spos4[g][i];
            off++;
        }
    }
}

// ============================================================================
// k_match: full (u=0) and NMS (u=1) in one launch. p-tiles of 1024, 8 chunks.
// blockIdx.y: u = y>>3, pc = y&7. 4 t/thread.
// grid (tc=16, y=16, g=16), block 128
// ============================================================================
__global__ void __launch_bounds__(128) k_match(){
    int tc = blockIdx.x, g = blockIdx.z;
    int u  = blockIdx.y >> 3, pc = blockIdx.y & 7;
    int Nt = g_Nt[g];
    int Npp = u ? g_Ns[g] : g_Np[g];
    int tcbase = tc*512;
    if (tcbase >= Nt) return;
    int pcbase = pc*1024;
    if (pcbase >= Npp) return;

    __shared__ float4 tile[1024];
    int lim = min(1024, Npp - pcbase);
    const float4* pp = u ? g_npos4[g] : g_ppos4[g];
    for (int k = threadIdx.x; k < lim; k += 128)
        tile[k] = pp[pcbase + k];
    __syncthreads();

    int tid = threadIdx.x;
    float tx[4], ty[4], tz[4], tb[4], d2m[4], sm[4];
    int ar[4]; bool tv[4]; int tg[4];
    #pragma unroll
    for (int q = 0; q < 4; q++){
        int t = tcbase + q*128 + tid;
        tg[q] = t; tv[q] = t < Nt;
        float4 T = tv[q] ? g_tpos4[g][t] : make_float4(0,0,0,0);
        tx[q]=T.x; ty[q]=T.y; tz[q]=T.z; tb[q]=T.w;
        d2m[q] = FINF; sm[q] = FINF; ar[q] = 0;
    }

    for (int k = 0; k < lim; k++){
        float4 f = tile[k];
        float d2v[4]; bool up[4]; bool any = false;
        #pragma unroll
        for (int q = 0; q < 4; q++){
            float ab = __fmaf_rn(f.z,tz[q],__fmaf_rn(f.y,ty[q],__fmul_rn(f.x,tx[q])));
            d2v[q] = __fsub_rn(__fadd_rn(tb[q],f.w), __fadd_rn(ab,ab));
            up[q] = d2v[q] < d2m[q];
            any = any | up[q];
        }
        if (__builtin_expect(any, 0)){
            #pragma unroll
            for (int q = 0; q < 4; q++){
                if (up[q]){
                    float s = sqrtf(fmaxf(d2v[q], 0.0f));
                    if (s < sm[q]){ sm[q] = s; ar[q] = pcbase + k; }
                    d2m[q] = d2v[q];
                }
            }
        }
    }

    #pragma unroll
    for (int q = 0; q < 4; q++){
        if (tv[q]){
            g_pd2[u][g][tg[q]][pc] = d2m[q];
            g_psm[u][g][tg[q]][pc] = sm[q];
            g_par[u][g][tg[q]][pc] = ar[q];
        }
    }
}

// ============================================================================
// k_matchc: chunk-combine (ascending pc keeps first-occurrence argmin;
// has = min d2 < thr2) + stable compaction of (ti,pi)/(ti_n,pi_n)
// ============================================================================
__global__ void __launch_bounds__(1024) k_matchc(){
    int g = blockIdx.x, t = threadIdx.x;
    int Nt = g_Nt[g];
    float thr = g_thr2[g & 1];
    int NpF = g_Np[g], NpN = g_Ns[g];

    int has0[8], arg0[8], has1[8], arg1[8];
    int c1 = 0, c2 = 0;
    #pragma unroll
    for (int r = 0; r < 8; r++){
        int i = t*8 + r;
        has0[r] = has1[r] = 0; arg0[r] = arg1[r] = 0;
        if (i < Nt){
            {
                float d2min = FINF, smin = FINF; int arg = 0;
                for (int pc = 0; pc < NPC; pc++){
                    if (pc*1024 < NpF){
                        float s = g_psm[0][g][i][pc];
                        if (s < smin){ smin = s; arg = g_par[0][g][i][pc]; }
                        d2min = fminf(d2min, g_pd2[0][g][i][pc]);
                    }
                }
                has0[r] = (d2min < thr); arg0[r] = arg;
            }
            {
                float d2min = FINF, smin = FINF; int arg = 0;
                for (int pc = 0; pc < NPC; pc++){
                    if (pc*1024 < NpN){
                        float s = g_psm[1][g][i][pc];
                        if (s < smin){ smin = s; arg = g_par[1][g][i][pc]; }
                        d2min = fminf(d2min, g_pd2[1][g][i][pc]);
                    }
                }
                has1[r] = (d2min < thr); arg1[r] = arg;
            }
            c1 += has0[r]; c2 += has1[r];
        }
    }

    __shared__ int s1[1024], s2[1024];
    s1[t] = c1; s2[t] = c2; __syncthreads();
    for (int o = 1; o < 1024; o <<= 1){
        int a = 0, b = 0;
        if (t >= o){ a = s1[t-o]; b = s2[t-o]; }
        __syncthreads();
        s1[t] += a; s2[t] += b;
        __syncthreads();
    }
    int o1 = s1[t] - c1, o2 = s2[t] - c2;
    if (t == 1023){ g_L[g] = s1[1023]; g_Ln[g] = s2[1023]; }
    #pragma unroll
    for (int r = 0; r < 8; r++){
        int i = t*8 + r;
        if (i < Nt){
            if (has0[r]){ g_ti [g][o1] = i; g_pi [g][o1] = arg0[r]; o1++; }
            if (has1[r]){ g_tin[g][o2] = i; g_pin[g][o2] = arg1[r]; o2++; }
        }
    }
}

// ============================================================================
// k_write: one block per (group, array); offsets recomputed per block
// ============================================================================
__global__ void __launch_bounds__(256) k_write(float* __restrict__ out){
    int g = blockIdx.x / 10, a = blockIdx.x % 10;
    __shared__ long long s_off;
    if (threadIdx.x == 0){
        long long cur = 0;
        for (int gg = 0; gg <= g; gg++){
            int Np = g_Np[gg], Ns = g_Ns[gg], Nt = g_Nt[gg], L = g_L[gg], Ln = g_Ln[gg];
            long long sz[10] = { (long long)Np*4, (long long)Ns*4, (long long)Nt*4,
                                 L, L, Ln, Ln,
                                 (long long)Np*3, (long long)Ns*3, (long long)Nt*3 };
            int amax = (gg == g) ? a : 10;
            for (int aa = 0; aa < amax; aa++) cur += sz[aa];
        }
        s_off = cur;
    }
    __syncthreads();
    long long off = s_off;

    int Np = g_Np[g], Ns = g_Ns[g], Nt = g_Nt[g], L = g_L[g], Ln = g_Ln[g];
    int n;
    switch (a){
        case 0: n = Np*4; break;
        case 1: n = Ns*4; break;
        case 2: n = Nt*4; break;
        case 3: case 4: n = L; break;
        case 5: case 6: n = Ln; break;
        case 7: n = Np*3; break;
        case 8: n = Ns*3; break;
        default: n = Nt*3; break;
    }
    const float* pp = (const float*)g_ppos4[g];
    const float* np = (const float*)g_npos4[g];
    const float* tp = (const float*)g_tpos4[g];
    for (int x = threadIdx.x; x < n; x += blockDim.x){
        float v;
        switch (a){
            case 0: v = g_pred [g][x>>2][x&3]; break;
            case 1: v = g_npred[g][x>>2][x&3]; break;
            case 2: v = g_tgt  [g][x>>2][x&3]; break;
            case 3: v = (float)g_ti [g][x]; break;
            case 4: v = (float)g_pi [g][x]; break;
            case 5: v = (float)g_tin[g][x]; break;
            case 6: v = (float)g_pin[g][x]; break;
            case 7: v = pp[(x/3)*4 + x%3]; break;
            case 8: v = np[(x/3)*4 + x%3]; break;
            default:v = tp[(x/3)*4 + x%3]; break;
        }
        out[off + x] = v;
    }
}

// ============================================================================
// Launch
// ============================================================================
extern "C" void kernel_launch(void* const* d_in, const int* in_sizes, int n_in,
                              void* d_out, int out_size){
    const float* P = (const float*)d_in[0];
    const float* T = (const float*)d_in[1];
    float* out = (float*)d_out;
    (void)in_sizes; (void)n_in; (void)out_size;

    k_maskcnt <<<dim3(32,16), 256>>>(P, T);
    k_coffs   <<<1, 32>>>();
    k_scat    <<<dim3(32,16), 256>>>(P, T);
    k_sort    <<<dim3(8,16), 512>>>();
    k_restrain<<<dim3(16,8,16), 256>>>();
    k_correct <<<dim3(16,16), 512>>>();
    k_nmsc    <<<16, 1024>>>();
    k_match   <<<dim3(16,16,16), 128>>>();
    k_matchc  <<<16, 1024>>>();
    k_write   <<<160, 256>>>(out);
}

// round 8
// speedup vs baseline: 3.0021x; 1.0272x over previous
#include <cuda_runtime.h>
#include <cstddef>

// ============================================================================
// Problem constants
// ============================================================================
#define NB   8
#define NE   2
#define NG   16
#define NC   8192
#define GMAX 8192
#define NW   (GMAX/32)     // 256 words per row
#define NPC  8             // match p-chunks of 1024
#define NBUK 2048          // sort buckets
#define FINF 3.4028235e38f

static __device__ __constant__ float c_LATX = 0.78125f;  // 25/32 exact
static __device__ __constant__ float c_LATY = 0.78125f;
static __device__ __constant__ float c_LATZ = 0.375f;    // 3/8 exact

// ============================================================================
// Device scratch (allocations forbidden -> __device__ globals)
// ============================================================================
__device__ float  g_pred [NG][GMAX][4];
__device__ float4 g_ppos4[NG][GMAX];      // x,y,z,|p|^2
__device__ float  g_tgt  [NG][GMAX][4];
__device__ float4 g_tpos4[NG][GMAX];
__device__ int g_Np[NG], g_Nt[NG];
__device__ int g_ccp[NG][32], g_cct[NG][32];
__device__ int g_cop[NG][32], g_cot[NG][32];

__device__ float  g_spred[NG][GMAX][4];   // sorted ascending by prob
__device__ float4 g_spos4[NG][GMAX];
__device__ int g_restrain[NG][GMAX];
__device__ int g_correct [NG][GMAX];

// packed decision bits: bit (i&31) of g_dbits[g][i>>5][j] = (d(i,j)<diam && i<j)
__device__ unsigned g_dbits[NG][NW][GMAX];

__device__ float  g_npred[NG][GMAX][4];   // NMS survivors
__device__ float4 g_npos4[NG][GMAX];
__device__ int g_Ns[NG];

// match partials per p-chunk (8 chunks of 1024), [0]=full, [1]=nms
__device__ float g_pd2[2][NG][GMAX][NPC];
__device__ float g_psm[2][NG][GMAX][NPC];
__device__ int   g_par[2][NG][GMAX][NPC];

__device__ int g_ti[NG][GMAX], g_pi[NG][GMAX];
__device__ int g_tin[NG][GMAX], g_pin[NG][GMAX];
__device__ int g_L[NG], g_Ln[NG];

__device__ float g_thr2[NE];

// ============================================================================
// Rounding-exact helpers (validated rel_err==0.0)
// ============================================================================
__device__ __forceinline__ float nrm3(float x,float y,float z){
    return __fadd_rn(__fadd_rn(__fmul_rn(x,x),__fmul_rn(y,y)),__fmul_rn(z,z));
}

// ============================================================================
// k_maskcnt: threshold-count per 256-cell chunk + zero restrain accumulators
// + bit-search d2 thresholds (fused)
// ============================================================================
__global__ void __launch_bounds__(256) k_maskcnt(const float* __restrict__ P,
                                                 const float* __restrict__ T){
    int chunk = blockIdx.x, g = blockIdx.y, b = g >> 1, e = g & 1;
    int tid = threadIdx.x;
    int zi = (g*32 + chunk)*256 + tid;
    ((int*)g_restrain)[zi] = 0;
    if (chunk == 0 && g == 0 && tid < NE){
        float diam = (tid==0) ? (float)(0.74*1.4) : (float)(0.528*1.4);
        float d2 = diam*diam;
        unsigned lo = __float_as_uint(d2*0.5f);
        unsigned hi = __float_as_uint(d2*2.0f);
        while (lo + 1u < hi){
            unsigned mid = lo + ((hi - lo) >> 1);
            if (sqrtf(__uint_as_float(mid)) >= diam) hi = mid; else lo = mid;
        }
        g_thr2[tid] = __uint_as_float(hi);
    }
    int c = chunk*256 + tid;
    size_t base = (((size_t)(b*NC + c))*2 + (size_t)e)*4;
    int mp = P[base+3] > 0.5f;
    int mt = T[base+3] > 0.5f;
    int cp = __syncthreads_count(mp);
    int ct = __syncthreads_count(mt);
    if (tid == 0){ g_ccp[g][chunk] = cp; g_cct[g][chunk] = ct; }
}

__global__ void k_coffs(){
    int g = threadIdx.x;
    if (g < NG){
        int op = 0, ot = 0;
        for (int c = 0; c < 32; c++){
            g_cop[g][c] = op; op += g_ccp[g][c];
            g_cot[g][c] = ot; ot += g_cct[g][c];
        }
        g_Np[g] = op; g_Nt[g] = ot;
    }
}

__global__ void __launch_bounds__(256) k_scat(const float* __restrict__ P,
                                              const float* __restrict__ T){
    int chunk = blockIdx.x, g = blockIdx.y, b = g >> 1, e = g & 1;
    int tid = threadIdx.x;
    int c = chunk*256 + tid;
    size_t idx4 = ((size_t)(b*NC + c))*2 + (size_t)e;
    float4 pv = ((const float4*)P)[idx4];
    float4 tv = ((const float4*)T)[idx4];
    int mp = pv.w > 0.5f;
    int mt = tv.w > 0.5f;

    unsigned bp = __ballot_sync(0xffffffffu, mp);
    unsigned bt = __ballot_sync(0xffffffffu, mt);
    int lane = tid & 31, w = tid >> 5;
    __shared__ int wpo[8], wto[8], wpc[8], wtc[8];
    if (lane == 0){ wpc[w] = __popc(bp); wtc[w] = __popc(bt); }
    __syncthreads();
    if (tid == 0){
        int a = 0, b2 = 0;
        for (int k = 0; k < 8; k++){ wpo[k] = a; a += wpc[k]; wto[k] = b2; b2 += wtc[k]; }
    }
    __syncthreads();

    int ci = c >> 8, cj = (c >> 3) & 31, ck = c & 7;
    unsigned ltm = (1u << lane) - 1u;
    if (mp){
        int o = g_cop[g][chunk] + wpo[w] + __popc(bp & ltm);
        g_pred[g][o][0] = pv.x; g_pred[g][o][1] = pv.y;
        g_pred[g][o][2] = pv.z; g_pred[g][o][3] = pv.w;
        float px = __fmul_rn(__fadd_rn(pv.x,(float)ci), c_LATX);
        float py = __fmul_rn(__fadd_rn(pv.y,(float)cj), c_LATY);
        float pz = __fmul_rn(__fadd_rn(pv.z,(float)ck), c_LATZ);
        g_ppos4[g][o] = make_float4(px,py,pz, nrm3(px,py,pz));
    }
    if (mt){
        int o = g_cot[g][chunk] + wto[w] + __popc(bt & ltm);
        g_tgt[g][o][0] = tv.x; g_tgt[g][o][1] = tv.y;
        g_tgt[g][o][2] = tv.z; g_tgt[g][o][3] = tv.w;
        float px = __fmul_rn(__fadd_rn(tv.x,(float)ci), c_LATX);
        float py = __fmul_rn(__fadd_rn(tv.y,(float)cj), c_LATY);
        float pz = __fmul_rn(__fadd_rn(tv.z,(float)ck), c_LATZ);
        g_tpos4[g][o] = make_float4(px,py,pz, nrm3(px,py,pz));
    }
}

// ============================================================================
// k_sort: exact stable ascending rank via monotone bucketing.
// Probs are > 0.5 (masked); v-0.5 is exact (Sterbenz), *4096 exact, so
// bucket = floor((v-0.5)*4096) is monotone nondecreasing in v; lower-bucket
// elements are provably < v, so rank = bucket_start + exact stable rank
// among same-bucket members (reference predicate). One block of 1024/group.
// ============================================================================
__global__ void __launch_bounds__(1024) k_sort(){
    int g = blockIdx.x;
    int Np = g_Np[g];
    int tid = threadIdx.x;
    __shared__ int cnts[NBUK];
    __shared__ int starts[NBUK];
    __shared__ unsigned short mem[GMAX];
    __shared__ int ps[1024];

    cnts[tid] = 0; cnts[tid + 1024] = 0;
    __syncthreads();
    for (int i = tid; i < Np; i += 1024){
        float v = g_pred[g][i][3];
        int b = (int)((v - 0.5f) * 4096.0f);
        b = min(max(b, 0), NBUK-1);
        atomicAdd(&cnts[b], 1);
    }
    __syncthreads();
    int c0 = cnts[2*tid], c1 = cnts[2*tid+1];
    int s = c0 + c1;
    ps[tid] = s; __syncthreads();
    for (int o = 1; o < 1024; o <<= 1){
        int a = (tid >= o) ? ps[tid-o] : 0;
        __syncthreads();
        ps[tid] += a;
        __syncthreads();
    }
    int excl = ps[tid] - s;
    starts[2*tid]   = excl;
    starts[2*tid+1] = excl + c0;
    cnts[2*tid] = 0; cnts[2*tid+1] = 0;   // reuse as fill cursors
    __syncthreads();
    for (int i = tid; i < Np; i += 1024){
        float v = g_pred[g][i][3];
        int b = (int)((v - 0.5f) * 4096.0f);
        b = min(max(b, 0), NBUK-1);
        int slot = starts[b] + atomicAdd(&cnts[b], 1);
        mem[slot] = (unsigned short)i;
    }
    __syncthreads();
    for (int i = tid; i < Np; i += 1024){
        float v = g_pred[g][i][3];
        int b = (int)((v - 0.5f) * 4096.0f);
        b = min(max(b, 0), NBUK-1);
        int st = starts[b], cn = cnts[b];
        int r = 0;
        for (int s2 = 0; s2 < cn; s2++){
            int j = mem[st + s2];
            float u = g_pred[g][j][3];
            r += (u < v) || (u == v && j < i);
        }
        int rank = st + r;
        g_spred[g][rank][0] = g_pred[g][i][0];
        g_spred[g][rank][1] = g_pred[g][i][1];
        g_spred[g][rank][2] = g_pred[g][i][2];
        g_spred[g][rank][3] = v;
        g_spos4[g][rank] = g_ppos4[g][i];
    }
}

// ============================================================================
// k_restrain: restrain[j] = #{i<j : d(i,j)<diam}, stores decision bits.
// i-tiles of 1024; triangle-bounded word loop; 4 j's/thread.
// grid (jc=8, is=8, g=16), block 256
// ============================================================================
__global__ void __launch_bounds__(256) k_restrain(){
    int jc = blockIdx.x, is = blockIdx.y, g = blockIdx.z;
    int Np = g_Np[g];
    int jcbase = jc*1024;
    if (jcbase >= Np) return;
    int jend = min(jcbase + 1024, Np);
    int isbase = is*1024;
    if (isbase >= jend) return;
    int wbase = isbase >> 5;

    __shared__ float4 tile[1024];
    int lim = min(1024, Np - isbase);
    for (int k = threadIdx.x; k < 1024; k += 256)
        tile[k] = (k < lim) ? g_spos4[g][isbase + k] : make_float4(0.f,0.f,0.f,FINF);
    __syncthreads();

    int tid = threadIdx.x;
    float thr = g_thr2[g & 1];
    int jq[4]; bool vq[4]; float4 Q[4]; int limq[4]; int cq[4];
    #pragma unroll
    for (int q = 0; q < 4; q++){
        jq[q] = jcbase + q*256 + tid;
        vq[q] = jq[q] < Np;
        Q[q] = vq[q] ? g_spos4[g][jq[q]] : make_float4(0,0,0,0);
        limq[q] = vq[q] ? max(0, min(jq[q] - isbase, 1024)) : 0;
        cq[q] = 0;
    }
    bool full = (isbase + 1024 <= jcbase);
    int ilim = min(lim, jend - isbase);
    int wcnt = (ilim + 31) >> 5;

    for (int wl = 0; wl < wcnt; wl++){
        unsigned bq[4] = {0,0,0,0};
        int kb = wl << 5;
        #pragma unroll
        for (int b = 0; b < 32; b++){
            float4 f = tile[kb + b];
            #pragma unroll
            for (int q = 0; q < 4; q++){
                float ab = __fmaf_rn(f.z,Q[q].z,__fmaf_rn(f.y,Q[q].y,__fmul_rn(f.x,Q[q].x)));
                float d2 = __fsub_rn(__fadd_rn(Q[q].w,f.w), __fadd_rn(ab,ab));
                if (d2 < thr) bq[q] |= (1u << b);
            }
        }
        if (full){
            #pragma unroll
            for (int q = 0; q < 4; q++){
                cq[q] += __popc(bq[q]);
                if (vq[q]) g_dbits[g][wbase + wl][jq[q]] = bq[q];
            }
        } else {
            #pragma unroll
            for (int q = 0; q < 4; q++){
                int r = limq[q] - kb;
                unsigned m = (r >= 32) ? 0xffffffffu : ((r > 0) ? ((1u << r) - 1u) : 0u);
                bq[q] &= m;
                cq[q] += __popc(bq[q]);
                if (m) g_dbits[g][wbase + wl][jq[q]] = bq[q];
            }
        }
    }
    #pragma unroll
    for (int q = 0; q < 4; q++)
        if (vq[q] && cq[q]) atomicAdd(&g_restrain[g][jq[q]], cq[q]);
}

// ============================================================================
// k_correct: correct[j] = popc(dbits[w][j] & nz_word[w]) over words below j
// ============================================================================
__global__ void __launch_bounds__(512) k_correct(){
    int g = blockIdx.y;
    int Np = g_Np[g];
    int tid = threadIdx.x;
    __shared__ unsigned nzw[NW];
    int lane = tid & 31, w = tid >> 5;
    #pragma unroll
    for (int pass = 0; pass < 16; pass++){
        int i = pass*512 + tid;
        int pred = (i < Np) && (g_restrain[g][i] != 0);
        unsigned bw = __ballot_sync(0xffffffffu, pred);
        if (lane == 0) nzw[pass*16 + w] = bw;
    }
    __syncthreads();
    int j = blockIdx.x*512 + tid;
    if (j >= Np) return;
    int nw = (j + 31) >> 5;
    int c = 0;
    #pragma unroll 4
    for (int w2 = 0; w2 < nw; w2++)
        c += __popc(g_dbits[g][w2][j] & nzw[w2]);
    g_correct[g][j] = c;
}

// ============================================================================
// k_nmsc: compact NMS survivors (sel = restrain==correct), stable
// ============================================================================
__global__ void __launch_bounds__(1024) k_nmsc(){
    int g = blockIdx.x, t = threadIdx.x;
    int Np = g_Np[g];
    __shared__ int sh[1024];
    int cnt = 0;
    #pragma unroll
    for (int r = 0; r < 8; r++){
        int i = t*8 + r;
        if (i < Np && g_restrain[g][i] == g_correct[g][i]) cnt++;
    }
    sh[t] = cnt; __syncthreads();
    for (int o = 1; o < 1024; o <<= 1){
        int a = 0;
        if (t >= o) a = sh[t-o];
        __syncthreads();
        sh[t] += a;
        __syncthreads();
    }
    int off = sh[t] - cnt;
    if (t == 1023) g_Ns[g] = sh[1023];
    #pragma unroll
    for (int r = 0; r < 8; r++){
        int i = t*8 + r;
        if (i < Np && g_restrain[g][i] == g_correct[g][i]){
            #pragma unroll
            for (int c = 0; c < 4; c++) g_npred[g][off][c] = g_spred[g][i][c];
            g_npos4[g][off] = g_spos4[g][i];
            off++;
        }
    }
}

// ============================================================================
// k_match: full (u=0) and NMS (u=1) in one launch. p-tiles of 1024 (8 chunks),
// t-chunks of 1024, 4 t/thread. blockIdx.y: u = y>>3, pc = y&7.
// grid (tc=8, y=16, g=16), block 256  -- tc=8 covers all 8192 targets
// ============================================================================
__global__ void __launch_bounds__(256) k_match(){
    int tc = blockIdx.x, g = blockIdx.z;
    int u  = blockIdx.y >> 3, pc = blockIdx.y & 7;
    int Nt = g_Nt[g];
    int Npp = u ? g_Ns[g] : g_Np[g];
    int tcbase = tc*1024;
    if (tcbase >= Nt) return;
    int pcbase = pc*1024;
    if (pcbase >= Npp) return;

    __shared__ float4 tile[1024];
    int lim = min(1024, Npp - pcbase);
    const float4* pp = u ? g_npos4[g] : g_ppos4[g];
    for (int k = threadIdx.x; k < lim; k += 256)
        tile[k] = pp[pcbase + k];
    __syncthreads();

    int tid = threadIdx.x;
    float tx[4], ty[4], tz[4], tb[4], d2m[4], sm[4];
    int ar[4]; bool tv[4]; int tg[4];
    #pragma unroll
    for (int q = 0; q < 4; q++){
        int t = tcbase + q*256 + tid;
        tg[q] = t; tv[q] = t < Nt;
        float4 T = tv[q] ? g_tpos4[g][t] : make_float4(0,0,0,0);
        tx[q]=T.x; ty[q]=T.y; tz[q]=T.z; tb[q]=T.w;
        d2m[q] = FINF; sm[q] = FINF; ar[q] = 0;
    }

    for (int k = 0; k < lim; k++){
        float4 f = tile[k];
        float d2v[4]; bool up[4]; bool any = false;
        #pragma unroll
        for (int q = 0; q < 4; q++){
            float ab = __fmaf_rn(f.z,tz[q],__fmaf_rn(f.y,ty[q],__fmul_rn(f.x,tx[q])));
            d2v[q] = __fsub_rn(__fadd_rn(tb[q],f.w), __fadd_rn(ab,ab));
            up[q] = d2v[q] < d2m[q];
            any = any | up[q];
        }
        if (__builtin_expect(any, 0)){
            #pragma unroll
            for (int q = 0; q < 4; q++){
                if (up[q]){
                    float s = sqrtf(fmaxf(d2v[q], 0.0f));
                    if (s < sm[q]){ sm[q] = s; ar[q] = pcbase + k; }
                    d2m[q] = d2v[q];
                }
            }
        }
    }

    #pragma unroll
    for (int q = 0; q < 4; q++){
        if (tv[q]){
            g_pd2[u][g][tg[q]][pc] = d2m[q];
            g_psm[u][g][tg[q]][pc] = sm[q];
            g_par[u][g][tg[q]][pc] = ar[q];
        }
    }
}

// ============================================================================
// k_matchc: chunk-combine (ascending pc keeps first-occurrence argmin;
// has = min d2 < thr2) + stable compaction of (ti,pi)/(ti_n,pi_n)
// ============================================================================
__global__ void __launch_bounds__(1024) k_matchc(){
    int g = blockIdx.x, t = threadIdx.x;
    int Nt = g_Nt[g];
    float thr = g_thr2[g & 1];
    int NpF = g_Np[g], NpN = g_Ns[g];

    int has0[8], arg0[8], has1[8], arg1[8];
    int c1 = 0, c2 = 0;
    #pragma unroll
    for (int r = 0; r < 8; r++){
        int i = t*8 + r;
        has0[r] = has1[r] = 0; arg0[r] = arg1[r] = 0;
        if (i < Nt){
            {
                float d2min = FINF, smin = FINF; int arg = 0;
                for (int pc = 0; pc < NPC; pc++){
                    if (pc*1024 < NpF){
                        float s = g_psm[0][g][i][pc];
                        if (s < smin){ smin = s; arg = g_par[0][g][i][pc]; }
                        d2min = fminf(d2min, g_pd2[0][g][i][pc]);
                    }
                }
                has0[r] = (d2min < thr); arg0[r] = arg;
            }
            {
                float d2min = FINF, smin = FINF; int arg = 0;
                for (int pc = 0; pc < NPC; pc++){
                    if (pc*1024 < NpN){
                        float s = g_psm[1][g][i][pc];
                        if (s < smin){ smin = s; arg = g_par[1][g][i][pc]; }
                        d2min = fminf(d2min, g_pd2[1][g][i][pc]);
                    }
                }
                has1[r] = (d2min < thr); arg1[r] = arg;
            }
            c1 += has0[r]; c2 += has1[r];
        }
    }

    __shared__ int s1[1024], s2[1024];
    s1[t] = c1; s2[t] = c2; __syncthreads();
    for (int o = 1; o < 1024; o <<= 1){
        int a = 0, b = 0;
        if (t >= o){ a = s1[t-o]; b = s2[t-o]; }
        __syncthreads();
        s1[t] += a; s2[t] += b;
        __syncthreads();
    }
    int o1 = s1[t] - c1, o2 = s2[t] - c2;
    if (t == 1023){ g_L[g] = s1[1023]; g_Ln[g] = s2[1023]; }
    #pragma unroll
    for (int r = 0; r < 8; r++){
        int i = t*8 + r;
        if (i < Nt){
            if (has0[r]){ g_ti [g][o1] = i; g_pi [g][o1] = arg0[r]; o1++; }
            if (has1[r]){ g_tin[g][o2] = i; g_pin[g][o2] = arg1[r]; o2++; }
        }
    }
}

// ============================================================================
// k_write: one block per (group, array); offsets recomputed per block
// ============================================================================
__global__ void __launch_bounds__(256) k_write(float* __restrict__ out){
    int g = blockIdx.x / 10, a = blockIdx.x % 10;
    __shared__ long long s_off;
    if (threadIdx.x == 0){
        long long cur = 0;
        for (int gg = 0; gg <= g; gg++){
            int Np = g_Np[gg], Ns = g_Ns[gg], Nt = g_Nt[gg], L = g_L[gg], Ln = g_Ln[gg];
            long long sz[10] = { (long long)Np*4, (long long)Ns*4, (long long)Nt*4,
                                 L, L, Ln, Ln,
                                 (long long)Np*3, (long long)Ns*3, (long long)Nt*3 };
            int amax = (gg == g) ? a : 10;
            for (int aa = 0; aa < amax; aa++) cur += sz[aa];
        }
        s_off = cur;
    }
    __syncthreads();
    long long off = s_off;

    int Np = g_Np[g], Ns = g_Ns[g], Nt = g_Nt[g], L = g_L[g], Ln = g_Ln[g];
    int n;
    switch (a){
        case 0: n = Np*4; break;
        case 1: n = Ns*4; break;
        case 2: n = Nt*4; break;
        case 3: case 4: n = L; break;
        case 5: case 6: n = Ln; break;
        case 7: n = Np*3; break;
        case 8: n = Ns*3; break;
        default: n = Nt*3; break;
    }
    const float* pp = (const float*)g_ppos4[g];
    const float* np = (const float*)g_npos4[g];
    const float* tp = (const float*)g_tpos4[g];
    for (int x = threadIdx.x; x < n; x += blockDim.x){
        float v;
        switch (a){
            case 0: v = g_pred [g][x>>2][x&3]; break;
            case 1: v = g_npred[g][x>>2][x&3]; break;
            case 2: v = g_tgt  [g][x>>2][x&3]; break;
            case 3: v = (float)g_ti [g][x]; break;
            case 4: v = (float)g_pi [g][x]; break;
            case 5: v = (float)g_tin[g][x]; break;
            case 6: v = (float)g_pin[g][x]; break;
            case 7: v = pp[(x/3)*4 + x%3]; break;
            case 8: v = np[(x/3)*4 + x%3]; break;
            default:v = tp[(x/3)*4 + x%3]; break;
        }
        out[off + x] = v;
    }
}

// ============================================================================
// Launch
// ============================================================================
extern "C" void kernel_launch(void* const* d_in, const int* in_sizes, int n_in,
                              void* d_out, int out_size){
    const float* P = (const float*)d_in[0];
    const float* T = (const float*)d_in[1];
    float* out = (float*)d_out;
    (void)in_sizes; (void)n_in; (void)out_size;

    k_maskcnt <<<dim3(32,16), 256>>>(P, T);
    k_coffs   <<<1, 32>>>();
    k_scat    <<<dim3(32,16), 256>>>(P, T);
    k_sort    <<<16, 1024>>>();
    k_restrain<<<dim3(8,8,16), 256>>>();
    k_correct <<<dim3(16,16), 512>>>();
    k_nmsc    <<<16, 1024>>>();
    k_match   <<<dim3(8,16,16), 256>>>();
    k_matchc  <<<16, 1024>>>();
    k_write   <<<160, 256>>>(out);
}

// round 9
// speedup vs baseline: 3.9086x; 1.3019x over previous
#include <cuda_runtime.h>
#include <cstddef>

// ============================================================================
// Problem constants
// ============================================================================
#define NB   8
#define NE   2
#define NG   16
#define NC   8192
#define GMAX 8192
#define NW   (GMAX/32)     // 256 words per row
#define NPC  8             // match p-chunks of 1024
#define NBUK 2048          // sort buckets
#define FINF 3.4028235e38f

static __device__ __constant__ float c_LATX = 0.78125f;  // 25/32 exact
static __device__ __constant__ float c_LATY = 0.78125f;
static __device__ __constant__ float c_LATZ = 0.375f;    // 3/8 exact

// ============================================================================
// Device scratch
// ============================================================================
__device__ float  g_pred [NG][GMAX][4];
__device__ float4 g_ppos4[NG][GMAX];      // x,y,z,|p|^2
__device__ float  g_tgt  [NG][GMAX][4];
__device__ float4 g_tpos4[NG][GMAX];
__device__ int g_Np[NG], g_Nt[NG];
__device__ int g_ccp[NG][32], g_cct[NG][32];
__device__ int g_cop[NG][32], g_cot[NG][32];

__device__ float  g_spred[NG][GMAX][4];   // sorted ascending by prob
__device__ float4 g_spos4[NG][GMAX];
__device__ int g_restrain[NG][GMAX];
__device__ int g_correct [NG][GMAX];

// packed decision bits: bit (i&31) of g_dbits[g][i>>5][j] = (d(i,j)<diam && i<j)
__device__ unsigned g_dbits[NG][NW][GMAX];

__device__ float  g_npred[NG][GMAX][4];   // NMS survivors
__device__ float4 g_npos4[NG][GMAX];
__device__ int g_Ns[NG];

// match partials per p-chunk (8 chunks of 1024), [0]=full, [1]=nms
__device__ float g_pd2[2][NG][GMAX][NPC];
__device__ float g_psm[2][NG][GMAX][NPC];
__device__ int   g_par[2][NG][GMAX][NPC];

__device__ int g_ti[NG][GMAX], g_pi[NG][GMAX];
__device__ int g_tin[NG][GMAX], g_pin[NG][GMAX];
__device__ int g_L[NG], g_Ln[NG];

__device__ float g_thr2[NE];

// ============================================================================
// Rounding-exact helpers (validated rel_err==0.0).
// f32x2 packed ops: two independent IEEE-rn fp32 lane ops -> bit-identical.
// d2 via fma(ab,-2,s): ab+ab is exact, so rn(s-2ab) == fsub(s, fadd(ab,ab)).
// ============================================================================
__device__ __forceinline__ float nrm3(float x,float y,float z){
    return __fadd_rn(__fadd_rn(__fmul_rn(x,x),__fmul_rn(y,y)),__fmul_rn(z,z));
}
__device__ __forceinline__ unsigned long long pk2(float lo, float hi){
    unsigned long long r;
    asm("mov.b64 %0, {%1, %2};" : "=l"(r)
        : "r"(__float_as_uint(lo)), "r"(__float_as_uint(hi)));
    return r;
}
__device__ __forceinline__ void upk2(unsigned long long v, float& lo, float& hi){
    unsigned a, b;
    asm("mov.b64 {%0, %1}, %2;" : "=r"(a), "=r"(b) : "l"(v));
    lo = __uint_as_float(a); hi = __uint_as_float(b);
}
__device__ __forceinline__ unsigned long long mul2(unsigned long long a, unsigned long long b){
    unsigned long long r;
    asm("mul.rn.f32x2 %0, %1, %2;" : "=l"(r) : "l"(a), "l"(b));
    return r;
}
__device__ __forceinline__ unsigned long long add2(unsigned long long a, unsigned long long b){
    unsigned long long r;
    asm("add.rn.f32x2 %0, %1, %2;" : "=l"(r) : "l"(a), "l"(b));
    return r;
}
__device__ __forceinline__ unsigned long long fma2(unsigned long long a, unsigned long long b,
                                                   unsigned long long c){
    unsigned long long r;
    asm("fma.rn.f32x2 %0, %1, %2, %3;" : "=l"(r) : "l"(a), "l"(b), "l"(c));
    return r;
}

// ============================================================================
// k_maskcnt: threshold-count per chunk + zero accumulators + thr2 bit-search
// ============================================================================
__global__ void __launch_bounds__(256) k_maskcnt(const float* __restrict__ P,
                                                 const float* __restrict__ T){
    int chunk = blockIdx.x, g = blockIdx.y, b = g >> 1, e = g & 1;
    int tid = threadIdx.x;
    int zi = (g*32 + chunk)*256 + tid;
    ((int*)g_restrain)[zi] = 0;
    if (chunk == 0 && g == 0 && tid < NE){
        float diam = (tid==0) ? (float)(0.74*1.4) : (float)(0.528*1.4);
        float d2 = diam*diam;
        unsigned lo = __float_as_uint(d2*0.5f);
        unsigned hi = __float_as_uint(d2*2.0f);
        while (lo + 1u < hi){
            unsigned mid = lo + ((hi - lo) >> 1);
            if (sqrtf(__uint_as_float(mid)) >= diam) hi = mid; else lo = mid;
        }
        g_thr2[tid] = __uint_as_float(hi);
    }
    int c = chunk*256 + tid;
    size_t base = (((size_t)(b*NC + c))*2 + (size_t)e)*4;
    int mp = P[base+3] > 0.5f;
    int mt = T[base+3] > 0.5f;
    int cp = __syncthreads_count(mp);
    int ct = __syncthreads_count(mt);
    if (tid == 0){ g_ccp[g][chunk] = cp; g_cct[g][chunk] = ct; }
}

__global__ void k_coffs(){
    int g = threadIdx.x;
    if (g < NG){
        int op = 0, ot = 0;
        for (int c = 0; c < 32; c++){
            g_cop[g][c] = op; op += g_ccp[g][c];
            g_cot[g][c] = ot; ot += g_cct[g][c];
        }
        g_Np[g] = op; g_Nt[g] = ot;
    }
}

__global__ void __launch_bounds__(256) k_scat(const float* __restrict__ P,
                                              const float* __restrict__ T){
    int chunk = blockIdx.x, g = blockIdx.y, b = g >> 1, e = g & 1;
    int tid = threadIdx.x;
    int c = chunk*256 + tid;
    size_t idx4 = ((size_t)(b*NC + c))*2 + (size_t)e;
    float4 pv = ((const float4*)P)[idx4];
    float4 tv = ((const float4*)T)[idx4];
    int mp = pv.w > 0.5f;
    int mt = tv.w > 0.5f;

    unsigned bp = __ballot_sync(0xffffffffu, mp);
    unsigned bt = __ballot_sync(0xffffffffu, mt);
    int lane = tid & 31, w = tid >> 5;
    __shared__ int wpo[8], wto[8], wpc[8], wtc[8];
    if (lane == 0){ wpc[w] = __popc(bp); wtc[w] = __popc(bt); }
    __syncthreads();
    if (tid == 0){
        int a = 0, b2 = 0;
        for (int k = 0; k < 8; k++){ wpo[k] = a; a += wpc[k]; wto[k] = b2; b2 += wtc[k]; }
    }
    __syncthreads();

    int ci = c >> 8, cj = (c >> 3) & 31, ck = c & 7;
    unsigned ltm = (1u << lane) - 1u;
    if (mp){
        int o = g_cop[g][chunk] + wpo[w] + __popc(bp & ltm);
        g_pred[g][o][0] = pv.x; g_pred[g][o][1] = pv.y;
        g_pred[g][o][2] = pv.z; g_pred[g][o][3] = pv.w;
        float px = __fmul_rn(__fadd_rn(pv.x,(float)ci), c_LATX);
        float py = __fmul_rn(__fadd_rn(pv.y,(float)cj), c_LATY);
        float pz = __fmul_rn(__fadd_rn(pv.z,(float)ck), c_LATZ);
        g_ppos4[g][o] = make_float4(px,py,pz, nrm3(px,py,pz));
    }
    if (mt){
        int o = g_cot[g][chunk] + wto[w] + __popc(bt & ltm);
        g_tgt[g][o][0] = tv.x; g_tgt[g][o][1] = tv.y;
        g_tgt[g][o][2] = tv.z; g_tgt[g][o][3] = tv.w;
        float px = __fmul_rn(__fadd_rn(tv.x,(float)ci), c_LATX);
        float py = __fmul_rn(__fadd_rn(tv.y,(float)cj), c_LATY);
        float pz = __fmul_rn(__fadd_rn(tv.z,(float)ck), c_LATZ);
        g_tpos4[g][o] = make_float4(px,py,pz, nrm3(px,py,pz));
    }
}

// ============================================================================
// k_sort: exact stable ascending rank via monotone bucketing (validated)
// ============================================================================
__global__ void __launch_bounds__(1024) k_sort(){
    int g = blockIdx.x;
    int Np = g_Np[g];
    int tid = threadIdx.x;
    __shared__ int cnts[NBUK];
    __shared__ int starts[NBUK];
    __shared__ unsigned short mem[GMAX];
    __shared__ int ps[1024];

    cnts[tid] = 0; cnts[tid + 1024] = 0;
    __syncthreads();
    for (int i = tid; i < Np; i += 1024){
        float v = g_pred[g][i][3];
        int b = (int)((v - 0.5f) * 4096.0f);
        b = min(max(b, 0), NBUK-1);
        atomicAdd(&cnts[b], 1);
    }
    __syncthreads();
    int c0 = cnts[2*tid], c1 = cnts[2*tid+1];
    int s = c0 + c1;
    ps[tid] = s; __syncthreads();
    for (int o = 1; o < 1024; o <<= 1){
        int a = (tid >= o) ? ps[tid-o] : 0;
        __syncthreads();
        ps[tid] += a;
        __syncthreads();
    }
    int excl = ps[tid] - s;
    starts[2*tid]   = excl;
    starts[2*tid+1] = excl + c0;
    cnts[2*tid] = 0; cnts[2*tid+1] = 0;
    __syncthreads();
    for (int i = tid; i < Np; i += 1024){
        float v = g_pred[g][i][3];
        int b = (int)((v - 0.5f) * 4096.0f);
        b = min(max(b, 0), NBUK-1);
        int slot = starts[b] + atomicAdd(&cnts[b], 1);
        mem[slot] = (unsigned short)i;
    }
    __syncthreads();
    for (int i = tid; i < Np; i += 1024){
        float v = g_pred[g][i][3];
        int b = (int)((v - 0.5f) * 4096.0f);
        b = min(max(b, 0), NBUK-1);
        int st = starts[b], cn = cnts[b];
        int r = 0;
        for (int s2 = 0; s2 < cn; s2++){
            int j = mem[st + s2];
            float u = g_pred[g][j][3];
            r += (u < v) || (u == v && j < i);
        }
        int rank = st + r;
        g_spred[g][rank][0] = g_pred[g][i][0];
        g_spred[g][rank][1] = g_pred[g][i][1];
        g_spred[g][rank][2] = g_pred[g][i][2];
        g_spred[g][rank][3] = v;
        g_spos4[g][rank] = g_ppos4[g][i];
    }
}

// ============================================================================
// k_restrain: restrain[j] + decision bits, packed f32x2 math.
// i-tiles of 512, j-chunks of 1024 (4 j's/thread = 2 packed pairs).
// grid (jc=8, is=16, g=16), block 256
// ============================================================================
__global__ void __launch_bounds__(256) k_restrain(){
    int jc = blockIdx.x, is = blockIdx.y, g = blockIdx.z;
    int Np = g_Np[g];
    int jcbase = jc*1024;
    if (jcbase >= Np) return;
    int jend = min(jcbase + 1024, Np);
    int isbase = is*512;
    if (isbase >= jend) return;
    int wbase = isbase >> 5;

    __shared__ float4 tile[512];
    int lim = min(512, Np - isbase);
    for (int k = threadIdx.x; k < 512; k += 256)
        tile[k] = (k < lim) ? g_spos4[g][isbase + k] : make_float4(0.f,0.f,0.f,FINF);
    __syncthreads();

    int tid = threadIdx.x;
    float thr = g_thr2[g & 1];
    int jq[4]; bool vq[4]; int limq[4]; int cq[4];
    float4 Q[4];
    #pragma unroll
    for (int q = 0; q < 4; q++){
        jq[q] = jcbase + q*256 + tid;
        vq[q] = jq[q] < Np;
        Q[q] = vq[q] ? g_spos4[g][jq[q]] : make_float4(0,0,0,0);
        limq[q] = vq[q] ? max(0, min(jq[q] - isbase, 512)) : 0;
        cq[q] = 0;
    }
    unsigned long long Qx01 = pk2(Q[0].x, Q[1].x), Qx23 = pk2(Q[2].x, Q[3].x);
    unsigned long long Qy01 = pk2(Q[0].y, Q[1].y), Qy23 = pk2(Q[2].y, Q[3].y);
    unsigned long long Qz01 = pk2(Q[0].z, Q[1].z), Qz23 = pk2(Q[2].z, Q[3].z);
    unsigned long long Qw01 = pk2(Q[0].w, Q[1].w), Qw23 = pk2(Q[2].w, Q[3].w);
    const unsigned long long NEG2 = pk2(-2.0f, -2.0f);

    bool full = (isbase + 512 <= jcbase);
    int ilim = min(lim, jend - isbase);
    int wcnt = (ilim + 31) >> 5;

    for (int wl = 0; wl < wcnt; wl++){
        unsigned bq[4] = {0,0,0,0};
        int kb = wl << 5;
        #pragma unroll
        for (int b = 0; b < 32; b++){
            float4 f = tile[kb + b];
            unsigned long long fx = pk2(f.x, f.x);
            unsigned long long fy = pk2(f.y, f.y);
            unsigned long long fz = pk2(f.z, f.z);
            unsigned long long fw = pk2(f.w, f.w);
            unsigned long long ab01 = fma2(fz, Qz01, fma2(fy, Qy01, mul2(fx, Qx01)));
            unsigned long long d01  = fma2(ab01, NEG2, add2(Qw01, fw));
            unsigned long long ab23 = fma2(fz, Qz23, fma2(fy, Qy23, mul2(fx, Qx23)));
            unsigned long long d23  = fma2(ab23, NEG2, add2(Qw23, fw));
            float d0, d1, d2, d3;
            upk2(d01, d0, d1);
            upk2(d23, d2, d3);
            if (d0 < thr) bq[0] |= (1u << b);
            if (d1 < thr) bq[1] |= (1u << b);
            if (d2 < thr) bq[2] |= (1u << b);
            if (d3 < thr) bq[3] |= (1u << b);
        }
        if (full){
            #pragma unroll
            for (int q = 0; q < 4; q++){
                cq[q] += __popc(bq[q]);
                if (vq[q]) g_dbits[g][wbase + wl][jq[q]] = bq[q];
            }
        } else {
            #pragma unroll
            for (int q = 0; q < 4; q++){
                int r = limq[q] - kb;
                unsigned m = (r >= 32) ? 0xffffffffu : ((r > 0) ? ((1u << r) - 1u) : 0u);
                bq[q] &= m;
                cq[q] += __popc(bq[q]);
                if (m) g_dbits[g][wbase + wl][jq[q]] = bq[q];
            }
        }
    }
    #pragma unroll
    for (int q = 0; q < 4; q++)
        if (vq[q] && cq[q]) atomicAdd(&g_restrain[g][jq[q]], cq[q]);
}

// ============================================================================
// k_correct: correct[j] = popc(dbits[w][j] & nz_word[w]) over words below j
// ============================================================================
__global__ void __launch_bounds__(512) k_correct(){
    int g = blockIdx.y;
    int Np = g_Np[g];
    int tid = threadIdx.x;
    __shared__ unsigned nzw[NW];
    int lane = tid & 31, w = tid >> 5;
    #pragma unroll
    for (int pass = 0; pass < 16; pass++){
        int i = pass*512 + tid;
        int pred = (i < Np) && (g_restrain[g][i] != 0);
        unsigned bw = __ballot_sync(0xffffffffu, pred);
        if (lane == 0) nzw[pass*16 + w] = bw;
    }
    __syncthreads();
    int j = blockIdx.x*512 + tid;
    if (j >= Np) return;
    int nw = (j + 31) >> 5;
    int c = 0;
    #pragma unroll 4
    for (int w2 = 0; w2 < nw; w2++)
        c += __popc(g_dbits[g][w2][j] & nzw[w2]);
    g_correct[g][j] = c;
}

// ============================================================================
// k_nmsc: compact NMS survivors (sel = restrain==correct), stable
// ============================================================================
__global__ void __launch_bounds__(1024) k_nmsc(){
    int g = blockIdx.x, t = threadIdx.x;
    int Np = g_Np[g];
    __shared__ int sh[1024];
    int cnt = 0;
    #pragma unroll
    for (int r = 0; r < 8; r++){
        int i = t*8 + r;
        if (i < Np && g_restrain[g][i] == g_correct[g][i]) cnt++;
    }
    sh[t] = cnt; __syncthreads();
    for (int o = 1; o < 1024; o <<= 1){
        int a = 0;
        if (t >= o) a = sh[t-o];
        __syncthreads();
        sh[t] += a;
        __syncthreads();
    }
    int off = sh[t] - cnt;
    if (t == 1023) g_Ns[g] = sh[1023];
    #pragma unroll
    for (int r = 0; r < 8; r++){
        int i = t*8 + r;
        if (i < Np && g_restrain[g][i] == g_correct[g][i]){
            #pragma unroll
            for (int c = 0; c < 4; c++) g_npred[g][off][c] = g_spred[g][i][c];
            g_npos4[g][off] = g_spos4[g][i];
            off++;
        }
    }
}

// ============================================================================
// k_match: full (u=0) and NMS (u=1) in one launch, packed f32x2 math.
// p-tiles of 1024 (8 chunks), t-chunks of 1024, 4 t/thread (2 packed pairs).
// blockIdx.y: u = y>>3, pc = y&7. grid (tc=8, y=16, g=16), block 256
// ============================================================================
__global__ void __launch_bounds__(256) k_match(){
    int tc = blockIdx.x, g = blockIdx.z;
    int u  = blockIdx.y >> 3, pc = blockIdx.y & 7;
    int Nt = g_Nt[g];
    int Npp = u ? g_Ns[g] : g_Np[g];
    int tcbase = tc*1024;
    if (tcbase >= Nt) return;
    int pcbase = pc*1024;
    if (pcbase >= Npp) return;

    __shared__ float4 tile[1024];
    int lim = min(1024, Npp - pcbase);
    const float4* pp = u ? g_npos4[g] : g_ppos4[g];
    for (int k = threadIdx.x; k < lim; k += 256)
        tile[k] = pp[pcbase + k];
    __syncthreads();

    int tid = threadIdx.x;
    float d2m[4], sm[4];
    int ar[4]; bool tv[4]; int tg[4];
    float4 T4[4];
    #pragma unroll
    for (int q = 0; q < 4; q++){
        int t = tcbase + q*256 + tid;
        tg[q] = t; tv[q] = t < Nt;
        T4[q] = tv[q] ? g_tpos4[g][t] : make_float4(0,0,0,0);
        d2m[q] = FINF; sm[q] = FINF; ar[q] = 0;
    }
    unsigned long long Tx01 = pk2(T4[0].x, T4[1].x), Tx23 = pk2(T4[2].x, T4[3].x);
    unsigned long long Ty01 = pk2(T4[0].y, T4[1].y), Ty23 = pk2(T4[2].y, T4[3].y);
    unsigned long long Tz01 = pk2(T4[0].z, T4[1].z), Tz23 = pk2(T4[2].z, T4[3].z);
    unsigned long long Tw01 = pk2(T4[0].w, T4[1].w), Tw23 = pk2(T4[2].w, T4[3].w);
    const unsigned long long NEG2 = pk2(-2.0f, -2.0f);

    for (int k = 0; k < lim; k++){
        float4 f = tile[k];
        unsigned long long fx = pk2(f.x, f.x);
        unsigned long long fy = pk2(f.y, f.y);
        unsigned long long fz = pk2(f.z, f.z);
        unsigned long long fw = pk2(f.w, f.w);
        unsigned long long ab01 = fma2(fz, Tz01, fma2(fy, Ty01, mul2(fx, Tx01)));
        unsigned long long d01  = fma2(ab01, NEG2, add2(Tw01, fw));
        unsigned long long ab23 = fma2(fz, Tz23, fma2(fy, Ty23, mul2(fx, Tx23)));
        unsigned long long d23  = fma2(ab23, NEG2, add2(Tw23, fw));
        float d2v[4];
        upk2(d01, d2v[0], d2v[1]);
        upk2(d23, d2v[2], d2v[3]);
        bool up0 = d2v[0] < d2m[0];
        bool up1 = d2v[1] < d2m[1];
        bool up2 = d2v[2] < d2m[2];
        bool up3 = d2v[3] < d2m[3];
        if (__builtin_expect(up0 | up1 | up2 | up3, 0)){
            bool up[4] = {up0, up1, up2, up3};
            #pragma unroll
            for (int q = 0; q < 4; q++){
                if (up[q]){
                    float s = sqrtf(fmaxf(d2v[q], 0.0f));
                    if (s < sm[q]){ sm[q] = s; ar[q] = pcbase + k; }
                    d2m[q] = d2v[q];
                }
            }
        }
    }

    #pragma unroll
    for (int q = 0; q < 4; q++){
        if (tv[q]){
            g_pd2[u][g][tg[q]][pc] = d2m[q];
            g_psm[u][g][tg[q]][pc] = sm[q];
            g_par[u][g][tg[q]][pc] = ar[q];
        }
    }
}

// ============================================================================
// k_matchc: chunk-combine + stable compaction of (ti,pi)/(ti_n,pi_n)
// ============================================================================
__global__ void __launch_bounds__(1024) k_matchc(){
    int g = blockIdx.x, t = threadIdx.x;
    int Nt = g_Nt[g];
    float thr = g_thr2[g & 1];
    int NpF = g_Np[g], NpN = g_Ns[g];

    int has0[8], arg0[8], has1[8], arg1[8];
    int c1 = 0, c2 = 0;
    #pragma unroll
    for (int r = 0; r < 8; r++){
        int i = t*8 + r;
        has0[r] = has1[r] = 0; arg0[r] = arg1[r] = 0;
        if (i < Nt){
            {
                float d2min = FINF, smin = FINF; int arg = 0;
                for (int pc = 0; pc < NPC; pc++){
                    if (pc*1024 < NpF){
                        float s = g_psm[0][g][i][pc];
                        if (s < smin){ smin = s; arg = g_par[0][g][i][pc]; }
                        d2min = fminf(d2min, g_pd2[0][g][i][pc]);
                    }
                }
                has0[r] = (d2min < thr); arg0[r] = arg;
            }
            {
                float d2min = FINF, smin = FINF; int arg = 0;
                for (int pc = 0; pc < NPC; pc++){
                    if (pc*1024 < NpN){
                        float s = g_psm[1][g][i][pc];
                        if (s < smin){ smin = s; arg = g_par[1][g][i][pc]; }
                        d2min = fminf(d2min, g_pd2[1][g][i][pc]);
                    }
                }
                has1[r] = (d2min < thr); arg1[r] = arg;
            }
            c1 += has0[r]; c2 += has1[r];
        }
    }

    __shared__ int s1[1024], s2[1024];
    s1[t] = c1; s2[t] = c2; __syncthreads();
    for (int o = 1; o < 1024; o <<= 1){
        int a = 0, b = 0;
        if (t >= o){ a = s1[t-o]; b = s2[t-o]; }
        __syncthreads();
        s1[t] += a; s2[t] += b;
        __syncthreads();
    }
    int o1 = s1[t] - c1, o2 = s2[t] - c2;
    if (t == 1023){ g_L[g] = s1[1023]; g_Ln[g] = s2[1023]; }
    #pragma unroll
    for (int r = 0; r < 8; r++){
        int i = t*8 + r;
        if (i < Nt){
            if (has0[r]){ g_ti [g][o1] = i; g_pi [g][o1] = arg0[r]; o1++; }
            if (has1[r]){ g_tin[g][o2] = i; g_pin[g][o2] = arg1[r]; o2++; }
        }
    }
}

// ============================================================================
// k_write: one block per (group, array); offsets recomputed per block
// ============================================================================
__global__ void __launch_bounds__(256) k_write(float* __restrict__ out){
    int g = blockIdx.x / 10, a = blockIdx.x % 10;
    __shared__ long long s_off;
    if (threadIdx.x == 0){
        long long cur = 0;
        for (int gg = 0; gg <= g; gg++){
            int Np = g_Np[gg], Ns = g_Ns[gg], Nt = g_Nt[gg], L = g_L[gg], Ln = g_Ln[gg];
            long long sz[10] = { (long long)Np*4, (long long)Ns*4, (long long)Nt*4,
                                 L, L, Ln, Ln,
                                 (long long)Np*3, (long long)Ns*3, (long long)Nt*3 };
            int amax = (gg == g) ? a : 10;
            for (int aa = 0; aa < amax; aa++) cur += sz[aa];
        }
        s_off = cur;
    }
    __syncthreads();
    long long off = s_off;

    int Np = g_Np[g], Ns = g_Ns[g], Nt = g_Nt[g], L = g_L[g], Ln = g_Ln[g];
    int n;
    switch (a){
        case 0: n = Np*4; break;
        case 1: n = Ns*4; break;
        case 2: n = Nt*4; break;
        case 3: case 4: n = L; break;
        case 5: case 6: n = Ln; break;
        case 7: n = Np*3; break;
        case 8: n = Ns*3; break;
        default: n = Nt*3; break;
    }
    const float* pp = (const float*)g_ppos4[g];
    const float* np = (const float*)g_npos4[g];
    const float* tp = (const float*)g_tpos4[g];
    for (int x = threadIdx.x; x < n; x += blockDim.x){
        float v;
        switch (a){
            case 0: v = g_pred [g][x>>2][x&3]; break;
            case 1: v = g_npred[g][x>>2][x&3]; break;
            case 2: v = g_tgt  [g][x>>2][x&3]; break;
            case 3: v = (float)g_ti [g][x]; break;
            case 4: v = (float)g_pi [g][x]; break;
            case 5: v = (float)g_tin[g][x]; break;
            case 6: v = (float)g_pin[g][x]; break;
            case 7: v = pp[(x/3)*4 + x%3]; break;
            case 8: v = np[(x/3)*4 + x%3]; break;
            default:v = tp[(x/3)*4 + x%3]; break;
        }
        out[off + x] = v;
    }
}

// ============================================================================
// Launch
// ============================================================================
extern "C" void kernel_launch(void* const* d_in, const int* in_sizes, int n_in,
                              void* d_out, int out_size){
    const float* P = (const float*)d_in[0];
    const float* T = (const float*)d_in[1];
    float* out = (float*)d_out;
    (void)in_sizes; (void)n_in; (void)out_size;

    k_maskcnt <<<dim3(32,16), 256>>>(P, T);
    k_coffs   <<<1, 32>>>();
    k_scat    <<<dim3(32,16), 256>>>(P, T);
    k_sort    <<<16, 1024>>>();
    k_restrain<<<dim3(8,16,16), 256>>>();
    k_correct <<<dim3(16,16), 512>>>();
    k_nmsc    <<<16, 1024>>>();
    k_match   <<<dim3(8,16,16), 256>>>();
    k_matchc  <<<16, 1024>>>();
    k_write   <<<160, 256>>>(out);
}

// round 10
// speedup vs baseline: 9.1290x; 2.3356x over previous
#include <cuda_runtime.h>
#include <cstddef>

// ============================================================================
// Problem constants
// ============================================================================
#define NB   8
#define NE   2
#define NG   16
#define NC   8192
#define GMAX 8192
#define NPCX 24
#define NBINS (24*24*2)    // 1152 spatial bins, width 25/24 >= max reach of thr
#define NBUK 2048          // sort buckets
#define FINF 3.4028235e38f

static __device__ __constant__ float c_LATX = 0.78125f;  // 25/32 exact
static __device__ __constant__ float c_LATY = 0.78125f;
static __device__ __constant__ float c_LATZ = 0.375f;    // 3/8 exact

// ============================================================================
// Device scratch
// ============================================================================
__device__ float  g_pred [NG][GMAX][4];
__device__ float4 g_ppos4[NG][GMAX];      // x,y,z,|p|^2 (cell order)
__device__ float  g_tgt  [NG][GMAX][4];
__device__ float4 g_tpos4[NG][GMAX];
__device__ int g_Np[NG], g_Nt[NG];
__device__ int g_ccp[NG][32], g_cct[NG][32];

__device__ float  g_spred[NG][GMAX][4];   // sorted ascending by prob
__device__ float4 g_spos4[NG][GMAX];
__device__ int g_restrain[NG][GMAX];
__device__ int g_correct [NG][GMAX];

__device__ float  g_npred[NG][GMAX][4];   // NMS survivors
__device__ float4 g_npos4[NG][GMAX];
__device__ int g_Ns[NG];

// spatial bins: S = sorted preds, P = cell-order preds, N = NMS survivors
__device__ unsigned short g_memS[NG][GMAX], g_memP[NG][GMAX], g_memN[NG][GMAX];
__device__ int g_bsS[NG][NBINS+1], g_bsP[NG][NBINS+1], g_bsN[NG][NBINS+1];

__device__ int g_thas [NG][GMAX], g_targ [NG][GMAX];
__device__ int g_thasn[NG][GMAX], g_targn[NG][GMAX];
__device__ int g_ti[NG][GMAX], g_pi[NG][GMAX];
__device__ int g_tin[NG][GMAX], g_pin[NG][GMAX];
__device__ int g_L[NG], g_Ln[NG];

__device__ float g_thr2[NE];

// ============================================================================
// Rounding-exact helpers (validated rel_err==0.0 across rounds 1-9)
// ============================================================================
__device__ __forceinline__ float nrm3(float x,float y,float z){
    return __fadd_rn(__fadd_rn(__fmul_rn(x,x),__fmul_rn(y,y)),__fmul_rn(z,z));
}
__device__ __forceinline__ float d2_exact(float4 f, float4 q){
    float ab = __fmaf_rn(f.z,q.z,__fmaf_rn(f.y,q.y,__fmul_rn(f.x,q.x)));
    return __fmaf_rn(ab, -2.0f, __fadd_rn(q.w, f.w));   // == (aa+bb) - 2ab (2ab exact)
}
__device__ __forceinline__ int binof(float4 p){
    int bx = min((int)(p.x * 0.96f), 23);
    int by = min((int)(p.y * 0.96f), 23);
    int bz = min((int)(p.z * 0.6666667f), 1);
    return (bx*24 + by)*2 + bz;
}

// ============================================================================
// Block-cooperative bin build. REQUIRES blockDim == 1024.
// Member order within a bin is nondeterministic (atomic cursors) but every
// consumer is order-invariant (counts; lexicographic argmin).
// ============================================================================
__device__ void build_bins_block(const float4* pos, int n, unsigned short* mem,
                                 int* gstart, int* bc, int* bs, int* ps){
    int tid = threadIdx.x;
    for (int b = tid; b < NBINS; b += 1024) bc[b] = 0;
    __syncthreads();
    for (int i = tid; i < n; i += 1024) atomicAdd(&bc[binof(pos[i])], 1);
    __syncthreads();
    int c0 = (2*tid   < NBINS) ? bc[2*tid]   : 0;
    int c1 = (2*tid+1 < NBINS) ? bc[2*tid+1] : 0;
    int s = c0 + c1;
    ps[tid] = s; __syncthreads();
    for (int o = 1; o < 1024; o <<= 1){
        int a = (tid >= o) ? ps[tid-o] : 0;
        __syncthreads();
        ps[tid] += a;
        __syncthreads();
    }
    int excl = ps[tid] - s;
    if (2*tid   < NBINS) bs[2*tid]   = excl;
    if (2*tid+1 < NBINS) bs[2*tid+1] = excl + c0;
    if (tid == 0) bs[NBINS] = n;
    __syncthreads();
    for (int b = tid; b < NBINS; b += 1024) bc[b] = bs[b];
    __syncthreads();
    for (int i = tid; i < n; i += 1024){
        int slot = atomicAdd(&bc[binof(pos[i])], 1);
        mem[slot] = (unsigned short)i;
    }
    for (int b = tid; b <= NBINS; b += 1024) gstart[b] = bs[b];
    __syncthreads();
}

// ============================================================================
// k_maskcnt: per-chunk mask counts + thr2 bit-search
// ============================================================================
__global__ void __launch_bounds__(256) k_maskcnt(const float* __restrict__ P,
                                                 const float* __restrict__ T){
    int chunk = blockIdx.x, g = blockIdx.y, b = g >> 1, e = g & 1;
    int tid = threadIdx.x;
    if (chunk == 0 && g == 0 && tid < NE){
        float diam = (tid==0) ? (float)(0.74*1.4) : (float)(0.528*1.4);
        float d2 = diam*diam;
        unsigned lo = __float_as_uint(d2*0.5f);
        unsigned hi = __float_as_uint(d2*2.0f);
        while (lo + 1u < hi){
            unsigned mid = lo + ((hi - lo) >> 1);
            if (sqrtf(__uint_as_float(mid)) >= diam) hi = mid; else lo = mid;
        }
        g_thr2[tid] = __uint_as_float(hi);
    }
    int c = chunk*256 + tid;
    size_t base = (((size_t)(b*NC + c))*2 + (size_t)e)*4;
    int mp = P[base+3] > 0.5f;
    int mt = T[base+3] > 0.5f;
    int cp = __syncthreads_count(mp);
    int ct = __syncthreads_count(mt);
    if (tid == 0){ g_ccp[g][chunk] = cp; g_cct[g][chunk] = ct; }
}

// ============================================================================
// k_scat: stable mask compaction (chunk offsets computed in-block) + positions
// ============================================================================
__global__ void __launch_bounds__(256) k_scat(const float* __restrict__ P,
                                              const float* __restrict__ T){
    int chunk = blockIdx.x, g = blockIdx.y, b = g >> 1, e = g & 1;
    int tid = threadIdx.x;
    int c = chunk*256 + tid;
    size_t idx4 = ((size_t)(b*NC + c))*2 + (size_t)e;
    float4 pv = ((const float4*)P)[idx4];
    float4 tv = ((const float4*)T)[idx4];
    int mp = pv.w > 0.5f;
    int mt = tv.w > 0.5f;

    unsigned bp = __ballot_sync(0xffffffffu, mp);
    unsigned bt = __ballot_sync(0xffffffffu, mt);
    int lane = tid & 31, w = tid >> 5;
    __shared__ int wpo[8], wto[8], wpc[8], wtc[8];
    __shared__ int s_op, s_ot;
    if (lane == 0){ wpc[w] = __popc(bp); wtc[w] = __popc(bt); }
    if (tid == 0){
        int op = 0, ot = 0;
        for (int k = 0; k < chunk; k++){ op += g_ccp[g][k]; ot += g_cct[g][k]; }
        s_op = op; s_ot = ot;
        if (chunk == 0){
            int tp = 0, tt = 0;
            for (int k = 0; k < 32; k++){ tp += g_ccp[g][k]; tt += g_cct[g][k]; }
            g_Np[g] = tp; g_Nt[g] = tt;
        }
    }
    __syncthreads();
    if (tid == 0){
        int a = 0, b2 = 0;
        for (int k = 0; k < 8; k++){ wpo[k] = a; a += wpc[k]; wto[k] = b2; b2 += wtc[k]; }
    }
    __syncthreads();

    int ci = c >> 8, cj = (c >> 3) & 31, ck = c & 7;
    unsigned ltm = (1u << lane) - 1u;
    if (mp){
        int o = s_op + wpo[w] + __popc(bp & ltm);
        g_pred[g][o][0] = pv.x; g_pred[g][o][1] = pv.y;
        g_pred[g][o][2] = pv.z; g_pred[g][o][3] = pv.w;
        float px = __fmul_rn(__fadd_rn(pv.x,(float)ci), c_LATX);
        float py = __fmul_rn(__fadd_rn(pv.y,(float)cj), c_LATY);
        float pz = __fmul_rn(__fadd_rn(pv.z,(float)ck), c_LATZ);
        g_ppos4[g][o] = make_float4(px,py,pz, nrm3(px,py,pz));
    }
    if (mt){
        int o = s_ot + wto[w] + __popc(bt & ltm);
        g_tgt[g][o][0] = tv.x; g_tgt[g][o][1] = tv.y;
        g_tgt[g][o][2] = tv.z; g_tgt[g][o][3] = tv.w;
        float px = __fmul_rn(__fadd_rn(tv.x,(float)ci), c_LATX);
        float py = __fmul_rn(__fadd_rn(tv.y,(float)cj), c_LATY);
        float pz = __fmul_rn(__fadd_rn(tv.z,(float)ck), c_LATZ);
        g_tpos4[g][o] = make_float4(px,py,pz, nrm3(px,py,pz));
    }
}

// ============================================================================
// k_sort: exact stable rank via monotone bucketing (validated) + build S/P bins
// ============================================================================
__global__ void __launch_bounds__(1024) k_sort(){
    int g = blockIdx.x;
    int Np = g_Np[g];
    int tid = threadIdx.x;
    __shared__ int cnts[NBUK];     // reused as bin counts/cursors
    __shared__ int starts[NBUK];   // reused as bin starts
    __shared__ unsigned short mem[GMAX];
    __shared__ int ps[1024];

    cnts[tid] = 0; cnts[tid + 1024] = 0;
    __syncthreads();
    for (int i = tid; i < Np; i += 1024){
        float v = g_pred[g][i][3];
        int b = (int)((v - 0.5f) * 4096.0f);
        b = min(max(b, 0), NBUK-1);
        atomicAdd(&cnts[b], 1);
    }
    __syncthreads();
    int c0 = cnts[2*tid], c1 = cnts[2*tid+1];
    int s = c0 + c1;
    ps[tid] = s; __syncthreads();
    for (int o = 1; o < 1024; o <<= 1){
        int a = (tid >= o) ? ps[tid-o] : 0;
        __syncthreads();
        ps[tid] += a;
        __syncthreads();
    }
    int excl = ps[tid] - s;
    starts[2*tid]   = excl;
    starts[2*tid+1] = excl + c0;
    cnts[2*tid] = 0; cnts[2*tid+1] = 0;
    __syncthreads();
    for (int i = tid; i < Np; i += 1024){
        float v = g_pred[g][i][3];
        int b = (int)((v - 0.5f) * 4096.0f);
        b = min(max(b, 0), NBUK-1);
        int slot = starts[b] + atomicAdd(&cnts[b], 1);
        mem[slot] = (unsigned short)i;
    }
    __syncthreads();
    for (int i = tid; i < Np; i += 1024){
        float v = g_pred[g][i][3];
        int b = (int)((v - 0.5f) * 4096.0f);
        b = min(max(b, 0), NBUK-1);
        int st = starts[b], cn = cnts[b];
        int r = 0;
        for (int s2 = 0; s2 < cn; s2++){
            int j = mem[st + s2];
            float u = g_pred[g][j][3];
            r += (u < v) || (u == v && j < i);
        }
        int rank = st + r;
        g_spred[g][rank][0] = g_pred[g][i][0];
        g_spred[g][rank][1] = g_pred[g][i][1];
        g_spred[g][rank][2] = g_pred[g][i][2];
        g_spred[g][rank][3] = v;
        g_spos4[g][rank] = g_ppos4[g][i];
    }
    __syncthreads();   // spos writes visible block-wide
    build_bins_block(g_spos4[g], Np, g_memS[g], g_bsS[g], cnts, starts, ps);
    build_bins_block(g_ppos4[g], Np, g_memP[g], g_bsP[g], cnts, starts, ps);
}

// ============================================================================
// k_restrain: restrain[j] = #{i<j : d2<thr2} via spatial bins (one thread/j)
// ============================================================================
__global__ void __launch_bounds__(256) k_restrain(){
    int g = blockIdx.y;
    int j = blockIdx.x*256 + threadIdx.x;
    int Np = g_Np[g];
    if (j >= Np) return;
    float thr = g_thr2[g & 1];
    float4 q = g_spos4[g][j];
    int bx = min((int)(q.x * 0.96f), 23);
    int by = min((int)(q.y * 0.96f), 23);
    int cnt = 0;
    for (int dx = max(bx-1,0); dx <= min(bx+1,23); dx++)
        for (int dy = max(by-1,0); dy <= min(by+1,23); dy++){
            int b0 = (dx*24 + dy)*2;
            int mhi = g_bsS[g][b0+2];
            for (int m = g_bsS[g][b0]; m < mhi; m++){
                int idx = g_memS[g][m];
                float4 f = g_spos4[g][idx];
                float d2 = d2_exact(f, q);
                cnt += (idx < j) && (d2 < thr);
            }
        }
    g_restrain[g][j] = cnt;
}

// ============================================================================
// k_correct: correct[j] = #{i<j : d2<thr2, restrain[i]!=0} via spatial bins
// ============================================================================
__global__ void __launch_bounds__(256) k_correct(){
    int g = blockIdx.y;
    int j = blockIdx.x*256 + threadIdx.x;
    int Np = g_Np[g];
    if (j >= Np) return;
    float thr = g_thr2[g & 1];
    float4 q = g_spos4[g][j];
    int bx = min((int)(q.x * 0.96f), 23);
    int by = min((int)(q.y * 0.96f), 23);
    int cnt = 0;
    for (int dx = max(bx-1,0); dx <= min(bx+1,23); dx++)
        for (int dy = max(by-1,0); dy <= min(by+1,23); dy++){
            int b0 = (dx*24 + dy)*2;
            int mhi = g_bsS[g][b0+2];
            for (int m = g_bsS[g][b0]; m < mhi; m++){
                int idx = g_memS[g][m];
                float4 f = g_spos4[g][idx];
                float d2 = d2_exact(f, q);
                cnt += (idx < j) && (d2 < thr) && (g_restrain[g][idx] != 0);
            }
        }
    g_correct[g][j] = cnt;
}

// ============================================================================
// k_nmsc: compact NMS survivors (sel = restrain==correct), stable + build N bins
// ============================================================================
__global__ void __launch_bounds__(1024) k_nmsc(){
    int g = blockIdx.x, t = threadIdx.x;
    int Np = g_Np[g];
    __shared__ int sh[1024];
    __shared__ int bc[NBINS];
    __shared__ int bs[NBINS+1];
    __shared__ int ps[1024];
    int cnt = 0;
    #pragma unroll
    for (int r = 0; r < 8; r++){
        int i = t*8 + r;
        if (i < Np && g_restrain[g][i] == g_correct[g][i]) cnt++;
    }
    sh[t] = cnt; __syncthreads();
    for (int o = 1; o < 1024; o <<= 1){
        int a = 0;
        if (t >= o) a = sh[t-o];
        __syncthreads();
        sh[t] += a;
        __syncthreads();
    }
    int off = sh[t] - cnt;
    if (t == 1023) g_Ns[g] = sh[1023];
    #pragma unroll
    for (int r = 0; r < 8; r++){
        int i = t*8 + r;
        if (i < Np && g_restrain[g][i] == g_correct[g][i]){
            #pragma unroll
            for (int c = 0; c < 4; c++) g_npred[g][off][c] = g_spred[g][i][c];
            g_npos4[g][off] = g_spos4[g][i];
            off++;
        }
    }
    __syncthreads();
    int Ns = sh[1023];
    build_bins_block(g_npos4[g], Ns, g_memN[g], g_bsN[g], bc, bs, ps);
}

// ============================================================================
// k_match: per-target has/argmin via spatial bins.
// has = any d2<thr2 (== any s<diam by thr2 construction). argmin restricted
// to d2<thr2 candidates (proven superset of the reference argmin set when
// has=true); lexicographic (s, idx) min == first-occurrence argmin of s row.
// grid (tc=32, u=2, g=16), block 256
// ============================================================================
__global__ void __launch_bounds__(256) k_match(){
    int g = blockIdx.z, u = blockIdx.y;
    int t = blockIdx.x*256 + threadIdx.x;
    int Nt = g_Nt[g];
    if (t >= Nt) return;
    const float4* pp = u ? g_npos4[g] : g_ppos4[g];
    const unsigned short* mem = u ? g_memN[g] : g_memP[g];
    const int* bst = u ? g_bsN[g] : g_bsP[g];
    float thr = g_thr2[g & 1];
    float4 q = g_tpos4[g][t];
    int bx = min((int)(q.x * 0.96f), 23);
    int by = min((int)(q.y * 0.96f), 23);
    int has = 0, arg = 0;
    float smin = FINF;
    for (int dx = max(bx-1,0); dx <= min(bx+1,23); dx++)
        for (int dy = max(by-1,0); dy <= min(by+1,23); dy++){
            int b0 = (dx*24 + dy)*2;
            int mhi = bst[b0+2];
            for (int m = bst[b0]; m < mhi; m++){
                int idx = mem[m];
                float4 f = pp[idx];
                float d2 = d2_exact(f, q);
                if (d2 < thr){
                    has = 1;
                    float s = sqrtf(fmaxf(d2, 0.0f));
                    if (s < smin || (s == smin && idx < arg)){ smin = s; arg = idx; }
                }
            }
        }
    if (u){ g_thasn[g][t] = has; g_targn[g][t] = arg; }
    else  { g_thas [g][t] = has; g_targ [g][t] = arg; }
}

// ============================================================================
// k_matchc: stable compaction of (ti,pi)/(ti_n,pi_n)
// ============================================================================
__global__ void __launch_bounds__(1024) k_matchc(){
    int g = blockIdx.x, t = threadIdx.x;
    int Nt = g_Nt[g];
    int has0[8], arg0[8], has1[8], arg1[8];
    int c1 = 0, c2 = 0;
    #pragma unroll
    for (int r = 0; r < 8; r++){
        int i = t*8 + r;
        has0[r] = has1[r] = 0; arg0[r] = arg1[r] = 0;
        if (i < Nt){
            has0[r] = g_thas [g][i]; arg0[r] = g_targ [g][i];
            has1[r] = g_thasn[g][i]; arg1[r] = g_targn[g][i];
            c1 += has0[r]; c2 += has1[r];
        }
    }
    __shared__ int s1[1024], s2[1024];
    s1[t] = c1; s2[t] = c2; __syncthreads();
    for (int o = 1; o < 1024; o <<= 1){
        int a = 0, b = 0;
        if (t >= o){ a = s1[t-o]; b = s2[t-o]; }
        __syncthreads();
        s1[t] += a; s2[t] += b;
        __syncthreads();
    }
    int o1 = s1[t] - c1, o2 = s2[t] - c2;
    if (t == 1023){ g_L[g] = s1[1023]; g_Ln[g] = s2[1023]; }
    #pragma unroll
    for (int r = 0; r < 8; r++){
        int i = t*8 + r;
        if (i < Nt){
            if (has0[r]){ g_ti [g][o1] = i; g_pi [g][o1] = arg0[r]; o1++; }
            if (has1[r]){ g_tin[g][o2] = i; g_pin[g][o2] = arg1[r]; o2++; }
        }
    }
}

// ============================================================================
// k_write: one block per (group, array); offsets recomputed per block
// ============================================================================
__global__ void __launch_bounds__(256) k_write(float* __restrict__ out){
    int g = blockIdx.x / 10, a = blockIdx.x % 10;
    __shared__ long long s_off;
    if (threadIdx.x == 0){
        long long cur = 0;
        for (int gg = 0; gg <= g; gg++){
            int Np = g_Np[gg], Ns = g_Ns[gg], Nt = g_Nt[gg], L = g_L[gg], Ln = g_Ln[gg];
            long long sz[10] = { (long long)Np*4, (long long)Ns*4, (long long)Nt*4,
                                 L, L, Ln, Ln,
                                 (long long)Np*3, (long long)Ns*3, (long long)Nt*3 };
            int amax = (gg == g) ? a : 10;
            for (int aa = 0; aa < amax; aa++) cur += sz[aa];
        }
        s_off = cur;
    }
    __syncthreads();
    long long off = s_off;

    int Np = g_Np[g], Ns = g_Ns[g], Nt = g_Nt[g], L = g_L[g], Ln = g_Ln[g];
    int n;
    switch (a){
        case 0: n = Np*4; break;
        case 1: n = Ns*4; break;
        case 2: n = Nt*4; break;
        case 3: case 4: n = L; break;
        case 5: case 6: n = Ln; break;
        case 7: n = Np*3; break;
        case 8: n = Ns*3; break;
        default: n = Nt*3; break;
    }
    const float* pp = (const float*)g_ppos4[g];
    const float* np = (const float*)g_npos4[g];
    const float* tp = (const float*)g_tpos4[g];
    for (int x = threadIdx.x; x < n; x += blockDim.x){
        float v;
        switch (a){
            case 0: v = g_pred [g][x>>2][x&3]; break;
            case 1: v = g_npred[g][x>>2][x&3]; break;
            case 2: v = g_tgt  [g][x>>2][x&3]; break;
            case 3: v = (float)g_ti [g][x]; break;
            case 4: v = (float)g_pi [g][x]; break;
            case 5: v = (float)g_tin[g][x]; break;
            case 6: v = (float)g_pin[g][x]; break;
            case 7: v = pp[(x/3)*4 + x%3]; break;
            case 8: v = np[(x/3)*4 + x%3]; break;
            default:v = tp[(x/3)*4 + x%3]; break;
        }
        out[off + x] = v;
    }
}

// ============================================================================
// Launch
// ============================================================================
extern "C" void kernel_launch(void* const* d_in, const int* in_sizes, int n_in,
                              void* d_out, int out_size){
    const float* P = (const float*)d_in[0];
    const float* T = (const float*)d_in[1];
    float* out = (float*)d_out;
    (void)in_sizes; (void)n_in; (void)out_size;

    k_maskcnt <<<dim3(32,16), 256>>>(P, T);
    k_scat    <<<dim3(32,16), 256>>>(P, T);
    k_sort    <<<16, 1024>>>();
    k_restrain<<<dim3(32,16), 256>>>();
    k_correct <<<dim3(32,16), 256>>>();
    k_nmsc    <<<16, 1024>>>();
    k_match   <<<dim3(32,2,16), 256>>>();
    k_matchc  <<<16, 1024>>>();
    k_write   <<<160, 256>>>(out);
}

// round 11
// speedup vs baseline: 9.8329x; 1.0771x over previous
#include <cuda_runtime.h>
#include <cstddef>

// ============================================================================
// Problem constants
// ============================================================================
#define NB   8
#define NE   2
#define NG   16
#define NC   8192
#define GMAX 8192
#define NBINS (24*24*2)    // spatial bins, width 25/24 >= max reach of thr
#define NBUK 2048          // sort buckets
#define FINF 3.4028235e38f

static __device__ __constant__ float c_LATX = 0.78125f;  // 25/32 exact
static __device__ __constant__ float c_LATY = 0.78125f;
static __device__ __constant__ float c_LATZ = 0.375f;    // 3/8 exact

// ============================================================================
// Device scratch
// ============================================================================
__device__ float  g_pred [NG][GMAX][4];
__device__ float4 g_ppos4[NG][GMAX];      // x,y,z,|p|^2 (cell order)
__device__ float  g_tgt  [NG][GMAX][4];
__device__ float4 g_tpos4[NG][GMAX];
__device__ int g_Np[NG], g_Nt[NG];

__device__ float  g_spred[NG][GMAX][4];   // sorted ascending by prob
__device__ float4 g_spos4[NG][GMAX];
__device__ int g_restrain[NG][GMAX];
__device__ int g_correct [NG][GMAX];

__device__ float  g_npred[NG][GMAX][4];   // NMS survivors
__device__ float4 g_npos4[NG][GMAX];
__device__ int g_Ns[NG];

// spatial bins: members (orig index) + positions copied into bin-slot order
__device__ unsigned short g_memS[NG][GMAX], g_memP[NG][GMAX];
__device__ unsigned short g_memN[NG][GMAX], g_memT[NG][GMAX];
__device__ float4 g_binS[NG][GMAX], g_binP[NG][GMAX];
__device__ float4 g_binN[NG][GMAX], g_binT[NG][GMAX];
__device__ int g_bsS[NG][NBINS+1], g_bsP[NG][NBINS+1];
__device__ int g_bsN[NG][NBINS+1], g_bsT[NG][NBINS+1];
__device__ unsigned char g_nzS[NG][GMAX];   // restrain!=0 in S-slot order

__device__ int g_thas [NG][GMAX], g_targ [NG][GMAX];
__device__ int g_thasn[NG][GMAX], g_targn[NG][GMAX];
__device__ int g_ti[NG][GMAX], g_pi[NG][GMAX];
__device__ int g_tin[NG][GMAX], g_pin[NG][GMAX];
__device__ int g_L[NG], g_Ln[NG];

__device__ float g_thr2[NE];

// ============================================================================
// Rounding-exact helpers (validated rel_err==0.0 across rounds 1-10)
// ============================================================================
__device__ __forceinline__ float nrm3(float x,float y,float z){
    return __fadd_rn(__fadd_rn(__fmul_rn(x,x),__fmul_rn(y,y)),__fmul_rn(z,z));
}
__device__ __forceinline__ float d2_exact(float4 f, float4 q){
    float ab = __fmaf_rn(f.z,q.z,__fmaf_rn(f.y,q.y,__fmul_rn(f.x,q.x)));
    return __fmaf_rn(ab, -2.0f, __fadd_rn(q.w, f.w));
}
__device__ __forceinline__ int binof(float4 p){
    int bx = min((int)(p.x * 0.96f), 23);
    int by = min((int)(p.y * 0.96f), 23);
    int bz = min((int)(p.z * 0.6666667f), 1);
    return (bx*24 + by)*2 + bz;
}

// ============================================================================
// Block-cooperative bin build (blockDim==1024). Fills member indices AND
// positions in bin-slot order. Slot order within a bin is nondeterministic
// (atomic cursors) but all consumers are order-invariant.
// ============================================================================
__device__ void build_bins_block(const float4* pos, int n, unsigned short* mem,
                                 float4* binpos, int* gstart,
                                 int* bc, int* bs, int* ps){
    int tid = threadIdx.x;
    for (int b = tid; b < NBINS; b += 1024) bc[b] = 0;
    __syncthreads();
    for (int i = tid; i < n; i += 1024) atomicAdd(&bc[binof(pos[i])], 1);
    __syncthreads();
    int c0 = (2*tid   < NBINS) ? bc[2*tid]   : 0;
    int c1 = (2*tid+1 < NBINS) ? bc[2*tid+1] : 0;
    int s = c0 + c1;
    ps[tid] = s; __syncthreads();
    for (int o = 1; o < 1024; o <<= 1){
        int a = (tid >= o) ? ps[tid-o] : 0;
        __syncthreads();
        ps[tid] += a;
        __syncthreads();
    }
    int excl = ps[tid] - s;
    if (2*tid   < NBINS) bs[2*tid]   = excl;
    if (2*tid+1 < NBINS) bs[2*tid+1] = excl + c0;
    if (tid == 0) bs[NBINS] = n;
    __syncthreads();
    for (int b = tid; b < NBINS; b += 1024) bc[b] = bs[b];
    __syncthreads();
    for (int i = tid; i < n; i += 1024){
        float4 p = pos[i];
        int slot = atomicAdd(&bc[binof(p)], 1);
        mem[slot] = (unsigned short)i;
        binpos[slot] = p;
    }
    for (int b = tid; b <= NBINS; b += 1024) gstart[b] = bs[b];
    __syncthreads();
}

// ============================================================================
// k_compact: fused threshold mask + stable compaction + positions + thr2
// One block of 1024 per group, 8 cells/thread (validated round-1 pattern).
// ============================================================================
__global__ void __launch_bounds__(1024) k_compact(const float* __restrict__ P,
                                                  const float* __restrict__ T){
    int g = blockIdx.x, b = g >> 1, e = g & 1, t = threadIdx.x;
    __shared__ int shp[1024], sht[1024];

    if (g == 0 && t < NE){
        float diam = (t==0) ? (float)(0.74*1.4) : (float)(0.528*1.4);
        float d2 = diam*diam;
        unsigned lo = __float_as_uint(d2*0.5f);
        unsigned hi = __float_as_uint(d2*2.0f);
        while (lo + 1u < hi){
            unsigned mid = lo + ((hi - lo) >> 1);
            if (sqrtf(__uint_as_float(mid)) >= diam) hi = mid; else lo = mid;
        }
        g_thr2[t] = __uint_as_float(hi);
    }

    float4 pv[8], tv[8];
    unsigned mpm = 0, mtm = 0;
    int cp = 0, ct = 0;
    #pragma unroll
    for (int r = 0; r < 8; r++){
        int c = t*8 + r;
        size_t idx4 = ((size_t)(b*NC + c))*2 + (size_t)e;
        pv[r] = ((const float4*)P)[idx4];
        tv[r] = ((const float4*)T)[idx4];
        if (pv[r].w > 0.5f){ mpm |= 1u << r; cp++; }
        if (tv[r].w > 0.5f){ mtm |= 1u << r; ct++; }
    }
    shp[t] = cp; sht[t] = ct; __syncthreads();
    for (int o = 1; o < 1024; o <<= 1){
        int a = 0, b2 = 0;
        if (t >= o){ a = shp[t-o]; b2 = sht[t-o]; }
        __syncthreads();
        shp[t] += a; sht[t] += b2;
        __syncthreads();
    }
    int op = shp[t] - cp, ot = sht[t] - ct;
    if (t == 1023){ g_Np[g] = shp[1023]; g_Nt[g] = sht[1023]; }

    #pragma unroll
    for (int r = 0; r < 8; r++){
        int c = t*8 + r;
        int ci = c >> 8, cj = (c >> 3) & 31, ck = c & 7;
        if ((mpm >> r) & 1u){
            g_pred[g][op][0]=pv[r].x; g_pred[g][op][1]=pv[r].y;
            g_pred[g][op][2]=pv[r].z; g_pred[g][op][3]=pv[r].w;
            float px = __fmul_rn(__fadd_rn(pv[r].x,(float)ci), c_LATX);
            float py = __fmul_rn(__fadd_rn(pv[r].y,(float)cj), c_LATY);
            float pz = __fmul_rn(__fadd_rn(pv[r].z,(float)ck), c_LATZ);
            g_ppos4[g][op] = make_float4(px,py,pz, nrm3(px,py,pz));
            op++;
        }
        if ((mtm >> r) & 1u){
            g_tgt[g][ot][0]=tv[r].x; g_tgt[g][ot][1]=tv[r].y;
            g_tgt[g][ot][2]=tv[r].z; g_tgt[g][ot][3]=tv[r].w;
            float px = __fmul_rn(__fadd_rn(tv[r].x,(float)ci), c_LATX);
            float py = __fmul_rn(__fadd_rn(tv[r].y,(float)cj), c_LATY);
            float pz = __fmul_rn(__fadd_rn(tv[r].z,(float)ck), c_LATZ);
            g_tpos4[g][ot] = make_float4(px,py,pz, nrm3(px,py,pz));
            ot++;
        }
    }
}

// ============================================================================
// k_sort: exact stable rank via monotone bucketing (validated) + build S/P/T bins
// ============================================================================
__global__ void __launch_bounds__(1024) k_sort(){
    int g = blockIdx.x;
    int Np = g_Np[g];
    int tid = threadIdx.x;
    __shared__ int cnts[NBUK];
    __shared__ int starts[NBUK];
    __shared__ unsigned short mem[GMAX];
    __shared__ int ps[1024];

    cnts[tid] = 0; cnts[tid + 1024] = 0;
    __syncthreads();
    for (int i = tid; i < Np; i += 1024){
        float v = g_pred[g][i][3];
        int b = (int)((v - 0.5f) * 4096.0f);
        b = min(max(b, 0), NBUK-1);
        atomicAdd(&cnts[b], 1);
    }
    __syncthreads();
    int c0 = cnts[2*tid], c1 = cnts[2*tid+1];
    int s = c0 + c1;
    ps[tid] = s; __syncthreads();
    for (int o = 1; o < 1024; o <<= 1){
        int a = (tid >= o) ? ps[tid-o] : 0;
        __syncthreads();
        ps[tid] += a;
        __syncthreads();
    }
    int excl = ps[tid] - s;
    starts[2*tid]   = excl;
    starts[2*tid+1] = excl + c0;
    cnts[2*tid] = 0; cnts[2*tid+1] = 0;
    __syncthreads();
    for (int i = tid; i < Np; i += 1024){
        float v = g_pred[g][i][3];
        int b = (int)((v - 0.5f) * 4096.0f);
        b = min(max(b, 0), NBUK-1);
        int slot = starts[b] + atomicAdd(&cnts[b], 1);
        mem[slot] = (unsigned short)i;
    }
    __syncthreads();
    for (int i = tid; i < Np; i += 1024){
        float v = g_pred[g][i][3];
        int b = (int)((v - 0.5f) * 4096.0f);
        b = min(max(b, 0), NBUK-1);
        int st = starts[b], cn = cnts[b];
        int r = 0;
        for (int s2 = 0; s2 < cn; s2++){
            int j = mem[st + s2];
            float u = g_pred[g][j][3];
            r += (u < v) || (u == v && j < i);
        }
        int rank = st + r;
        g_spred[g][rank][0] = g_pred[g][i][0];
        g_spred[g][rank][1] = g_pred[g][i][1];
        g_spred[g][rank][2] = g_pred[g][i][2];
        g_spred[g][rank][3] = v;
        g_spos4[g][rank] = g_ppos4[g][i];
    }
    __syncthreads();
    build_bins_block(g_spos4[g], Np,       g_memS[g], g_binS[g], g_bsS[g], cnts, starts, ps);
    build_bins_block(g_ppos4[g], Np,       g_memP[g], g_binP[g], g_bsP[g], cnts, starts, ps);
    build_bins_block(g_tpos4[g], g_Nt[g],  g_memT[g], g_binT[g], g_bsT[g], cnts, starts, ps);
}

// ============================================================================
// k_restrain: one thread per S-bin slot (warp-coherent traversal).
// Contiguous dy*dz neighbor range per dx. Writes restrain[j] and nzS[slot].
// ============================================================================
__global__ void __launch_bounds__(256) k_restrain(){
    int g = blockIdx.y;
    int s = blockIdx.x*256 + threadIdx.x;
    int Np = g_Np[g];
    if (s >= Np) return;
    float thr = g_thr2[g & 1];
    float4 q = g_binS[g][s];
    int j = g_memS[g][s];
    int bx = min((int)(q.x * 0.96f), 23);
    int by = min((int)(q.y * 0.96f), 23);
    int ylo = max(by-1,0), yhi = min(by+1,23);
    int cnt = 0;
    for (int dx = max(bx-1,0); dx <= min(bx+1,23); dx++){
        int mlo = g_bsS[g][(dx*24 + ylo)*2];
        int mhi = g_bsS[g][(dx*24 + yhi)*2 + 2];
        for (int m = mlo; m < mhi; m++){
            float4 f = g_binS[g][m];
            float d2 = d2_exact(f, q);
            int idx = g_memS[g][m];
            cnt += (idx < j) && (d2 < thr);
        }
    }
    g_restrain[g][j] = cnt;
    g_nzS[g][s] = (cnt != 0);
}

// ============================================================================
// k_correct: one thread per S-bin slot; nz read in slot order (no gather).
// ============================================================================
__global__ void __launch_bounds__(256) k_correct(){
    int g = blockIdx.y;
    int s = blockIdx.x*256 + threadIdx.x;
    int Np = g_Np[g];
    if (s >= Np) return;
    float thr = g_thr2[g & 1];
    float4 q = g_binS[g][s];
    int j = g_memS[g][s];
    int bx = min((int)(q.x * 0.96f), 23);
    int by = min((int)(q.y * 0.96f), 23);
    int ylo = max(by-1,0), yhi = min(by+1,23);
    int cnt = 0;
    for (int dx = max(bx-1,0); dx <= min(bx+1,23); dx++){
        int mlo = g_bsS[g][(dx*24 + ylo)*2];
        int mhi = g_bsS[g][(dx*24 + yhi)*2 + 2];
        for (int m = mlo; m < mhi; m++){
            float4 f = g_binS[g][m];
            float d2 = d2_exact(f, q);
            int idx = g_memS[g][m];
            cnt += (idx < j) && (d2 < thr) && (g_nzS[g][m] != 0);
        }
    }
    g_correct[g][j] = cnt;
}

// ============================================================================
// k_nmsc: compact NMS survivors (sel = restrain==correct), stable + build N bins
// ============================================================================
__global__ void __launch_bounds__(1024) k_nmsc(){
    int g = blockIdx.x, t = threadIdx.x;
    int Np = g_Np[g];
    __shared__ int sh[1024];
    __shared__ int bc[NBINS];
    __shared__ int bs[NBINS+1];
    __shared__ int ps[1024];
    int cnt = 0;
    #pragma unroll
    for (int r = 0; r < 8; r++){
        int i = t*8 + r;
        if (i < Np && g_restrain[g][i] == g_correct[g][i]) cnt++;
    }
    sh[t] = cnt; __syncthreads();
    for (int o = 1; o < 1024; o <<= 1){
        int a = 0;
        if (t >= o) a = sh[t-o];
        __syncthreads();
        sh[t] += a;
        __syncthreads();
    }
    int off = sh[t] - cnt;
    if (t == 1023) g_Ns[g] = sh[1023];
    #pragma unroll
    for (int r = 0; r < 8; r++){
        int i = t*8 + r;
        if (i < Np && g_restrain[g][i] == g_correct[g][i]){
            #pragma unroll
            for (int c = 0; c < 4; c++) g_npred[g][off][c] = g_spred[g][i][c];
            g_npos4[g][off] = g_spos4[g][i];
            off++;
        }
    }
    __syncthreads();
    int Ns = sh[1023];
    build_bins_block(g_npos4[g], Ns, g_memN[g], g_binN[g], g_bsN[g], bc, bs, ps);
}

// ============================================================================
// k_match: one thread per T-bin slot (warp-coherent). has = any d2<thr2;
// argmin = lexicographic (s, idx) over d2<thr2 candidates (proven exact).
// grid (tc=32, u=2, g=16), block 256
// ============================================================================
__global__ void __launch_bounds__(256) k_match(){
    int g = blockIdx.z, u = blockIdx.y;
    int s = blockIdx.x*256 + threadIdx.x;
    int Nt = g_Nt[g];
    if (s >= Nt) return;
    const float4* bin = u ? g_binN[g] : g_binP[g];
    const unsigned short* mem = u ? g_memN[g] : g_memP[g];
    const int* bst = u ? g_bsN[g] : g_bsP[g];
    float thr = g_thr2[g & 1];
    float4 q = g_binT[g][s];
    int t = g_memT[g][s];
    int bx = min((int)(q.x * 0.96f), 23);
    int by = min((int)(q.y * 0.96f), 23);
    int ylo = max(by-1,0), yhi = min(by+1,23);
    int has = 0, arg = 0;
    float smin = FINF;
    for (int dx = max(bx-1,0); dx <= min(bx+1,23); dx++){
        int mlo = bst[(dx*24 + ylo)*2];
        int mhi = bst[(dx*24 + yhi)*2 + 2];
        for (int m = mlo; m < mhi; m++){
            float4 f = bin[m];
            float d2 = d2_exact(f, q);
            if (d2 < thr){
                has = 1;
                int idx = mem[m];
                float sv = sqrtf(fmaxf(d2, 0.0f));
                if (sv < smin || (sv == smin && idx < arg)){ smin = sv; arg = idx; }
            }
        }
    }
    if (u){ g_thasn[g][t] = has; g_targn[g][t] = arg; }
    else  { g_thas [g][t] = has; g_targ [g][t] = arg; }
}

// ============================================================================
// k_matchc: stable compaction of (ti,pi)/(ti_n,pi_n)
// ============================================================================
__global__ void __launch_bounds__(1024) k_matchc(){
    int g = blockIdx.x, t = threadIdx.x;
    int Nt = g_Nt[g];
    int has0[8], arg0[8], has1[8], arg1[8];
    int c1 = 0, c2 = 0;
    #pragma unroll
    for (int r = 0; r < 8; r++){
        int i = t*8 + r;
        has0[r] = has1[r] = 0; arg0[r] = arg1[r] = 0;
        if (i < Nt){
            has0[r] = g_thas [g][i]; arg0[r] = g_targ [g][i];
            has1[r] = g_thasn[g][i]; arg1[r] = g_targn[g][i];
            c1 += has0[r]; c2 += has1[r];
        }
    }
    __shared__ int s1[1024], s2[1024];
    s1[t] = c1; s2[t] = c2; __syncthreads();
    for (int o = 1; o < 1024; o <<= 1){
        int a = 0, b = 0;
        if (t >= o){ a = s1[t-o]; b = s2[t-o]; }
        __syncthreads();
        s1[t] += a; s2[t] += b;
        __syncthreads();
    }
    int o1 = s1[t] - c1, o2 = s2[t] - c2;
    if (t == 1023){ g_L[g] = s1[1023]; g_Ln[g] = s2[1023]; }
    #pragma unroll
    for (int r = 0; r < 8; r++){
        int i = t*8 + r;
        if (i < Nt){
            if (has0[r]){ g_ti [g][o1] = i; g_pi [g][o1] = arg0[r]; o1++; }
            if (has1[r]){ g_tin[g][o2] = i; g_pin[g][o2] = arg1[r]; o2++; }
        }
    }
}

// ============================================================================
// k_write: one block per (group, array); offsets recomputed per block
// ============================================================================
__global__ void __launch_bounds__(256) k_write(float* __restrict__ out){
    int g = blockIdx.x / 10, a = blockIdx.x % 10;
    __shared__ long long s_off;
    if (threadIdx.x == 0){
        long long cur = 0;
        for (int gg = 0; gg <= g; gg++){
            int Np = g_Np[gg], Ns = g_Ns[gg], Nt = g_Nt[gg], L = g_L[gg], Ln = g_Ln[gg];
            long long sz[10] = { (long long)Np*4, (long long)Ns*4, (long long)Nt*4,
                                 L, L, Ln, Ln,
                                 (long long)Np*3, (long long)Ns*3, (long long)Nt*3 };
            int amax = (gg == g) ? a : 10;
            for (int aa = 0; aa < amax; aa++) cur += sz[aa];
        }
        s_off = cur;
    }
    __syncthreads();
    long long off = s_off;

    int Np = g_Np[g], Ns = g_Ns[g], Nt = g_Nt[g], L = g_L[g], Ln = g_Ln[g];
    int n;
    switch (a){
        case 0: n = Np*4; break;
        case 1: n = Ns*4; break;
        case 2: n = Nt*4; break;
        case 3: case 4: n = L; break;
        case 5: case 6: n = Ln; break;
        case 7: n = Np*3; break;
        case 8: n = Ns*3; break;
        default: n = Nt*3; break;
    }
    const float* pp = (const float*)g_ppos4[g];
    const float* np = (const float*)g_npos4[g];
    const float* tp = (const float*)g_tpos4[g];
    for (int x = threadIdx.x; x < n; x += blockDim.x){
        float v;
        switch (a){
            case 0: v = g_pred [g][x>>2][x&3]; break;
            case 1: v = g_npred[g][x>>2][x&3]; break;
            case 2: v = g_tgt  [g][x>>2][x&3]; break;
            case 3: v = (float)g_ti [g][x]; break;
            case 4: v = (float)g_pi [g][x]; break;
            case 5: v = (float)g_tin[g][x]; break;
            case 6: v = (float)g_pin[g][x]; break;
            case 7: v = pp[(x/3)*4 + x%3]; break;
            case 8: v = np[(x/3)*4 + x%3]; break;
            default:v = tp[(x/3)*4 + x%3]; break;
        }
        out[off + x] = v;
    }
}

// ============================================================================
// Launch
// ============================================================================
extern "C" void kernel_launch(void* const* d_in, const int* in_sizes, int n_in,
                              void* d_out, int out_size){
    const float* P = (const float*)d_in[0];
    const float* T = (const float*)d_in[1];
    float* out = (float*)d_out;
    (void)in_sizes; (void)n_in; (void)out_size;

    k_compact <<<16, 1024>>>(P, T);
    k_sort    <<<16, 1024>>>();
    k_restrain<<<dim3(32,16), 256>>>();
    k_correct <<<dim3(32,16), 256>>>();
    k_nmsc    <<<16, 1024>>>();
    k_match   <<<dim3(32,2,16), 256>>>();
    k_matchc  <<<16, 1024>>>();
    k_write   <<<160, 256>>>(out);
}